// round 6
// baseline (speedup 1.0000x reference)
#include <cuda_runtime.h>
#include <math.h>
#include <stdint.h>

// Problem constants
#define S_LEN 2048
#define HID   1024
#define NHEAD 16
#define HDIM  64
#define SH    (S_LEN * HID)
#define SCL2  0.1803368801111204f   // (1/sqrt(64)) * log2(e)
#define LOG2E 1.4426950408889634f

// ---------------------------------------------------------------------------
// Scratch
// ---------------------------------------------------------------------------
__device__ float g_wt[9 * HID * HID];   // 9 transposed tf32 weights [n][k]
__device__ float g_hs_t[SH];
__device__ float g_past_t[2 * SH];
__device__ float g_q[SH];
__device__ float g_k[SH];
__device__ float g_v[SH];
__device__ float g_ctx_t[SH];
__device__ float g_out[SH];
__device__ float g_out_t[SH];
__device__ float g_rq[SH];
__device__ float g_rk[2 * SH];
__device__ float g_rv[2 * SH];
__device__ float g_rctx[2 * SH];
__device__ float g_rec[SH];
__device__ float g_rec_t[SH];

// ---------------------------------------------------------------------------
// helpers
// ---------------------------------------------------------------------------
__device__ __forceinline__ unsigned f2tf32(float x) {
    unsigned r;
    asm("cvt.rna.tf32.f32 %0, %1;" : "=r"(r) : "f"(x));
    return r;
}
__device__ __forceinline__ uint4 cvt4(float4 v) {
    uint4 r;
    r.x = f2tf32(v.x); r.y = f2tf32(v.y);
    r.z = f2tf32(v.z); r.w = f2tf32(v.w);
    return r;
}
__device__ __forceinline__ void mma8(float* c, const unsigned* a, const unsigned* b) {
    asm volatile(
        "mma.sync.aligned.m16n8k8.row.col.f32.tf32.tf32.f32 "
        "{%0,%1,%2,%3}, {%4,%5,%6,%7}, {%8,%9}, {%0,%1,%2,%3};\n"
        : "+f"(c[0]), "+f"(c[1]), "+f"(c[2]), "+f"(c[3])
        : "r"(a[0]), "r"(a[1]), "r"(a[2]), "r"(a[3]), "r"(b[0]), "r"(b[1]));
}
__device__ __forceinline__ void ldsm4(unsigned &r0, unsigned &r1,
                                      unsigned &r2, unsigned &r3, unsigned a) {
    asm volatile("ldmatrix.sync.aligned.m8n8.x4.shared.b16 {%0,%1,%2,%3}, [%4];"
        : "=r"(r0), "=r"(r1), "=r"(r2), "=r"(r3) : "r"(a));
}
__device__ __forceinline__ unsigned sptr(const void* p) {
    return (unsigned)__cvta_generic_to_shared(p);
}
__device__ __forceinline__ float ex2f(float x) {
    float y; asm("ex2.approx.ftz.f32 %0, %1;" : "=f"(y) : "f"(x)); return y;
}
#define CP_ASYNC16(dst, src) \
    asm volatile("cp.async.cg.shared.global [%0], [%1], 16;" :: "r"(dst), "l"(src) : "memory")
#define CP_COMMIT() asm volatile("cp.async.commit_group;" ::: "memory")
#define CP_WAIT0()  asm volatile("cp.async.wait_group 0;" ::: "memory")

// ---------------------------------------------------------------------------
// Prep kernels
// ---------------------------------------------------------------------------
struct P9 { const float* p[9]; };

// Transpose + round 1024x1024 weights: dst[z][n][k] = tf32(src[z][k][n])
__global__ void __launch_bounds__(256) prep_wt_kernel(P9 ws, float* __restrict__ dst)
{
    __shared__ float t[32][33];
    const float* __restrict__ src = ws.p[blockIdx.z];
    float* __restrict__ d = dst + (size_t)blockIdx.z * HID * HID;
    const int r0 = blockIdx.y * 32, c0 = blockIdx.x * 32;
    const int lr = threadIdx.x >> 3, lc = (threadIdx.x & 7) * 4;

    float4 v = *(const float4*)&src[(size_t)(r0 + lr) * HID + c0 + lc];
    t[lr][lc] = v.x; t[lr][lc + 1] = v.y; t[lr][lc + 2] = v.z; t[lr][lc + 3] = v.w;
    __syncthreads();

    uint4 w;
    w.x = f2tf32(t[lc + 0][lr]);
    w.y = f2tf32(t[lc + 1][lr]);
    w.z = f2tf32(t[lc + 2][lr]);
    w.w = f2tf32(t[lc + 3][lr]);
    *(uint4*)&d[(size_t)(c0 + lr) * HID + r0 + lc] = w;
}

// Elementwise round to tf32 bits
__global__ void prep_rnd_kernel(const float4* __restrict__ s,
                                float4* __restrict__ d, int n4)
{
    int i = blockIdx.x * blockDim.x + threadIdx.x;
    if (i < n4) *(uint4*)&d[i] = cvt4(s[i]);
}

// ---------------------------------------------------------------------------
// GEMM (all-tf32-pre-rounded): C[M,N] = A[M,K] @ Bt[N,K]^T + bias
// 64x128 tile, BK=32, 8 warps (warp 32x32). cp.async double buffer,
// ldmatrix for A and B fragments. Optional tf32 copy C2; rnd rounds C.
// ---------------------------------------------------------------------------
#define TP 36                        // tile pitch words (32 + 4); rows 16B aligned
#define GSTAGE ((64 + 128) * TP)     // words per stage
#define GSMEM  (2 * GSTAGE * 4)

struct GJob { const float* A; const float* Bt; const float* bias;
              float* C; float* C2; int rnd; int pad; };
struct GJ3 { GJob j[3]; };

__global__ void __launch_bounds__(256) gemm_tt_kernel(GJ3 gj, int M, int N, int K)
{
    extern __shared__ unsigned sm[];
    const GJob jb = gj.j[blockIdx.z];

    const int tid  = threadIdx.x;
    const int warp = tid >> 5;
    const int lane = tid & 31;
    const int m0 = blockIdx.y * 64;
    const int n0 = blockIdx.x * 128;
    const int wm0 = (warp >> 2) * 32;
    const int wn0 = (warp & 3) * 32;

    // cp.async mappings
    const float* Ag = jb.A  + (size_t)(m0 + (tid >> 2)) * K + (tid & 3) * 8;
    const float* Bg = jb.Bt + (size_t)(n0 + (tid >> 1)) * K + (tid & 1) * 16;
    const unsigned smb = sptr(sm);
    const unsigned sa = smb + (((tid >> 2) * TP) + (tid & 3) * 8) * 4;
    const unsigned sb = smb + ((64 * TP) + (tid >> 1) * TP + (tid & 1) * 16) * 4;

    // ldmatrix lane decomposition
    const int lr  = (lane & 7) + ((lane >> 3) & 1) * 8;
    const int lc  = ((lane >> 4) & 1) * 4;
    const int brr = ((lane >> 4) & 1) * 8 + (lane & 7);
    const int bcc = ((lane >> 3) & 1) * 4;

    float acc[2][4][4];
    #pragma unroll
    for (int mt = 0; mt < 2; mt++)
        #pragma unroll
        for (int nt = 0; nt < 4; nt++)
            #pragma unroll
            for (int i = 0; i < 4; i++) acc[mt][nt][i] = 0.0f;

    // prologue: stage 0
    {
        CP_ASYNC16(sa,      Ag);
        CP_ASYNC16(sa + 16, Ag + 4);
        #pragma unroll
        for (int j = 0; j < 4; j++) CP_ASYNC16(sb + j * 16, Bg + j * 4);
        CP_COMMIT();
    }

    const int T = K / 32;
    for (int t = 0; t < T; t++) {
        const int buf = t & 1;
        CP_WAIT0();
        __syncthreads();
        if (t + 1 < T) {
            const unsigned off = (unsigned)((buf ^ 1) * GSTAGE) * 4;
            const int kn = (t + 1) * 32;
            CP_ASYNC16(sa + off,      Ag + kn);
            CP_ASYNC16(sa + off + 16, Ag + kn + 4);
            #pragma unroll
            for (int j = 0; j < 4; j++) CP_ASYNC16(sb + off + j * 16, Bg + kn + j * 4);
            CP_COMMIT();
        }

        const unsigned ab = smb + (unsigned)(buf * GSTAGE + (wm0 + lr) * TP + lc) * 4;
        const unsigned bb = smb + (unsigned)(buf * GSTAGE + 64 * TP + (wn0 + brr) * TP + bcc) * 4;
        #pragma unroll
        for (int ks = 0; ks < 4; ks++) {
            unsigned a0[4], a1[4];
            ldsm4(a0[0], a0[1], a0[2], a0[3], ab + (unsigned)(ks * 8) * 4);
            ldsm4(a1[0], a1[1], a1[2], a1[3], ab + (unsigned)(16 * TP + ks * 8) * 4);
            #pragma unroll
            for (int ntp = 0; ntp < 2; ntp++) {
                unsigned b0, b1, b2, b3;
                ldsm4(b0, b1, b2, b3, bb + (unsigned)(ntp * 16 * TP + ks * 8) * 4);
                unsigned ba[2] = {b0, b1}, bx[2] = {b2, b3};
                mma8(acc[0][2 * ntp],     a0, ba);
                mma8(acc[0][2 * ntp + 1], a0, bx);
                mma8(acc[1][2 * ntp],     a1, ba);
                mma8(acc[1][2 * ntp + 1], a1, bx);
            }
        }
    }

    #pragma unroll
    for (int mt = 0; mt < 2; mt++) {
        #pragma unroll
        for (int nt = 0; nt < 4; nt++) {
            int r0 = m0 + wm0 + mt * 16 + (lane >> 2);
            int c0 = n0 + wn0 + nt * 8 + 2 * (lane & 3);
            float b0 = jb.bias[c0], b1 = jb.bias[c0 + 1];
            float v0 = acc[mt][nt][0] + b0, v1 = acc[mt][nt][1] + b1;
            float v2 = acc[mt][nt][2] + b0, v3 = acc[mt][nt][3] + b1;
            size_t p0 = (size_t)r0 * N + c0;
            size_t p1 = (size_t)(r0 + 8) * N + c0;
            if (jb.C2) {
                uint2 u0 = {f2tf32(v0), f2tf32(v1)};
                uint2 u1 = {f2tf32(v2), f2tf32(v3)};
                *(uint2*)&jb.C2[p0] = u0;
                *(uint2*)&jb.C2[p1] = u1;
            }
            if (jb.rnd) {
                v0 = __uint_as_float(f2tf32(v0));
                v1 = __uint_as_float(f2tf32(v1));
                v2 = __uint_as_float(f2tf32(v2));
                v3 = __uint_as_float(f2tf32(v3));
            }
            float2 w0 = {v0, v1}, w1 = {v2, v3};
            *(float2*)&jb.C[p0] = w0;
            *(float2*)&jb.C[p1] = w1;
        }
    }
}

// ---------------------------------------------------------------------------
// Fused gate GEMM: gpre = [out_t|rec_t] @ WgT^T + bg (K=2048), then
// dst = out + sigmoid(gpre) * (rec - out). Same pipeline as gemm_tt.
// ---------------------------------------------------------------------------
__global__ void __launch_bounds__(256) gemm_gate_kernel(
    const float* __restrict__ outT, const float* __restrict__ recT,
    const float* __restrict__ WgT_lo, const float* __restrict__ WgT_hi,
    const float* __restrict__ bias,
    const float* __restrict__ outF, const float* __restrict__ recF,
    float* __restrict__ dst, int N)
{
    extern __shared__ unsigned sm[];

    const int tid  = threadIdx.x;
    const int warp = tid >> 5;
    const int lane = tid & 31;
    const int m0 = blockIdx.y * 64;
    const int n0 = blockIdx.x * 128;
    const int wm0 = (warp >> 2) * 32;
    const int wn0 = (warp & 3) * 32;

    const size_t aoff = (size_t)(m0 + (tid >> 2)) * HID + (tid & 3) * 8;
    const size_t boff = (size_t)(n0 + (tid >> 1)) * HID + (tid & 1) * 16;
    const unsigned smb = sptr(sm);
    const unsigned sa = smb + (((tid >> 2) * TP) + (tid & 3) * 8) * 4;
    const unsigned sb = smb + ((64 * TP) + (tid >> 1) * TP + (tid & 1) * 16) * 4;

    const int lr  = (lane & 7) + ((lane >> 3) & 1) * 8;
    const int lc  = ((lane >> 4) & 1) * 4;
    const int brr = ((lane >> 4) & 1) * 8 + (lane & 7);
    const int bcc = ((lane >> 3) & 1) * 4;

    float acc[2][4][4];
    #pragma unroll
    for (int mt = 0; mt < 2; mt++)
        #pragma unroll
        for (int nt = 0; nt < 4; nt++)
            #pragma unroll
            for (int i = 0; i < 4; i++) acc[mt][nt][i] = 0.0f;

    // prologue stage 0 (k = 0 -> lo half)
    {
        CP_ASYNC16(sa,      outT + aoff);
        CP_ASYNC16(sa + 16, outT + aoff + 4);
        #pragma unroll
        for (int j = 0; j < 4; j++) CP_ASYNC16(sb + j * 16, WgT_lo + boff + j * 4);
        CP_COMMIT();
    }

    const int T = (2 * HID) / 32;
    for (int t = 0; t < T; t++) {
        const int buf = t & 1;
        CP_WAIT0();
        __syncthreads();
        if (t + 1 < T) {
            const unsigned off = (unsigned)((buf ^ 1) * GSTAGE) * 4;
            const int kn = (t + 1) * 32;
            const int ka = kn & (HID - 1);
            const float* Asrc = (kn < HID) ? outT : recT;
            const float* Bsrc = (kn < HID) ? WgT_lo : WgT_hi;
            CP_ASYNC16(sa + off,      Asrc + aoff + ka);
            CP_ASYNC16(sa + off + 16, Asrc + aoff + ka + 4);
            #pragma unroll
            for (int j = 0; j < 4; j++) CP_ASYNC16(sb + off + j * 16, Bsrc + boff + ka + j * 4);
            CP_COMMIT();
        }

        const unsigned ab = smb + (unsigned)(buf * GSTAGE + (wm0 + lr) * TP + lc) * 4;
        const unsigned bb = smb + (unsigned)(buf * GSTAGE + 64 * TP + (wn0 + brr) * TP + bcc) * 4;
        #pragma unroll
        for (int ks = 0; ks < 4; ks++) {
            unsigned a0[4], a1[4];
            ldsm4(a0[0], a0[1], a0[2], a0[3], ab + (unsigned)(ks * 8) * 4);
            ldsm4(a1[0], a1[1], a1[2], a1[3], ab + (unsigned)(16 * TP + ks * 8) * 4);
            #pragma unroll
            for (int ntp = 0; ntp < 2; ntp++) {
                unsigned b0, b1, b2, b3;
                ldsm4(b0, b1, b2, b3, bb + (unsigned)(ntp * 16 * TP + ks * 8) * 4);
                unsigned ba[2] = {b0, b1}, bx[2] = {b2, b3};
                mma8(acc[0][2 * ntp],     a0, ba);
                mma8(acc[0][2 * ntp + 1], a0, bx);
                mma8(acc[1][2 * ntp],     a1, ba);
                mma8(acc[1][2 * ntp + 1], a1, bx);
            }
        }
    }

    #pragma unroll
    for (int mt = 0; mt < 2; mt++) {
        #pragma unroll
        for (int nt = 0; nt < 4; nt++) {
            int r0 = m0 + wm0 + mt * 16 + (lane >> 2);
            int c0 = n0 + wn0 + nt * 8 + 2 * (lane & 3);
            float b0 = bias[c0], b1 = bias[c0 + 1];
            float gp0 = acc[mt][nt][0] + b0, gp1 = acc[mt][nt][1] + b1;
            float gp2 = acc[mt][nt][2] + b0, gp3 = acc[mt][nt][3] + b1;
            size_t p0 = (size_t)r0 * N + c0;
            size_t p1 = (size_t)(r0 + 8) * N + c0;
            float2 o0 = *(const float2*)&outF[p0];
            float2 o1 = *(const float2*)&outF[p1];
            float2 rc0 = *(const float2*)&recF[p0];
            float2 rc1 = *(const float2*)&recF[p1];
            float gg0 = 1.0f / (1.0f + ex2f(-gp0 * LOG2E));
            float gg1 = 1.0f / (1.0f + ex2f(-gp1 * LOG2E));
            float gg2 = 1.0f / (1.0f + ex2f(-gp2 * LOG2E));
            float gg3 = 1.0f / (1.0f + ex2f(-gp3 * LOG2E));
            float2 w0 = {o0.x + gg0 * (rc0.x - o0.x), o0.y + gg1 * (rc0.y - o0.y)};
            float2 w1 = {o1.x + gg2 * (rc1.x - o1.x), o1.y + gg3 * (rc1.y - o1.y)};
            *(float2*)&dst[p0] = w0;
            *(float2*)&dst[p1] = w1;
        }
    }
}

// ---------------------------------------------------------------------------
// Flash attention: 256 thr (8 warps), 128 queries/block, key tiles of 64.
// ldmatrix everywhere; K double-buffered via cp.async; V transposed with
// XOR swizzle (2-way max conflict). blockIdx.z offsets K/V/O by z*SH.
// Output written tf32-rounded.
// ---------------------------------------------------------------------------
#define PW 68
#define ATTN_WORDS ((128 + 2 * 64 + 64) * PW)
#define ATTN_SMEM  (ATTN_WORDS * 4)

__global__ void __launch_bounds__(256, 2) attn_t_kernel(
    const float* __restrict__ Q, const float* __restrict__ K,
    const float* __restrict__ V, float* __restrict__ O)
{
    extern __shared__ unsigned sm[];
    unsigned* QP = sm;                       // [128][PW] Q then P
    unsigned* KB = sm + 128 * PW;            // 2 x [64][PW]
    unsigned* VT = sm + (128 + 128) * PW;    // [64][PW] d-major, swizzled

    const size_t zoff = (size_t)blockIdx.z * SH;
    K += zoff; V += zoff; O += zoff;

    const int tid  = threadIdx.x;
    const int warp = tid >> 5;
    const int lane = tid & 31;
    const int hoff = blockIdx.y * HDIM;
    const int q0   = blockIdx.x * 128;

    const int lr  = (lane & 7) + ((lane >> 3) & 1) * 8;
    const int lc  = ((lane >> 4) & 1) * 4;
    const int brr = ((lane >> 4) & 1) * 8 + (lane & 7);
    const int bcc = ((lane >> 3) & 1) * 4;

    const int krow = tid >> 2;
    const int kcol = (tid & 3) * 16;

    // Stage Q (natural)
    {
        const int row = tid >> 1, half = tid & 1;
        const uint4* Qg = (const uint4*)(Q + (size_t)(q0 + row) * HID + hoff) + half * 8;
        uint4* Qs = (uint4*)&QP[row * PW + half * 32];
        #pragma unroll
        for (int j = 0; j < 8; j++) Qs[j] = Qg[j];
    }

    // Prologue K tile 0
    {
        unsigned d = sptr(&KB[krow * PW + kcol]);
        const float* g = K + (size_t)krow * HID + hoff + kcol;
        #pragma unroll
        for (int i = 0; i < 4; i++) CP_ASYNC16(d + i * 16, g + i * 4);
        CP_COMMIT();
    }
    __syncthreads();

    unsigned qa[8][4];
    {
        unsigned base = sptr(&QP[(warp * 16 + lr) * PW + lc]);
        #pragma unroll
        for (int g = 0; g < 8; g++)
            ldsm4(qa[g][0], qa[g][1], qa[g][2], qa[g][3], base + g * 32);
    }

    float o[8][4];
    #pragma unroll
    for (int nt = 0; nt < 8; nt++)
        #pragma unroll
        for (int i = 0; i < 4; i++) o[nt][i] = 0.0f;
    float mrow0 = -1e30f, mrow1 = -1e30f, lrow0 = 0.0f, lrow1 = 0.0f;

    const unsigned pbase  = sptr(&QP[(warp * 16 + lr) * PW + lc]);
    const unsigned vtbase = sptr(&VT[brr * PW]);
    const int vswz = (tid & 3) << 2;               // store swizzle (d>>4)<<2

    for (int tile = 0; tile < S_LEN / 64; tile++) {
        const int buf = tile & 1;

        uint4 vr[4];
        {
            const uint4* Vg = (const uint4*)(V + (size_t)(tile * 64 + krow) * HID + hoff + kcol);
            #pragma unroll
            for (int i = 0; i < 4; i++) vr[i] = Vg[i];
        }

        CP_WAIT0();
        __syncthreads();

        // transpose V into VT with XOR swizzle
        {
            const int col = krow ^ vswz;
            #pragma unroll
            for (int i = 0; i < 16; i++) {
                int d = (tid & 3) * 16 + i;
                VT[d * PW + col] = ((const unsigned*)vr)[i];
            }
        }

        if (tile + 1 < S_LEN / 64) {
            unsigned d = sptr(&KB[(buf ^ 1) * 64 * PW + krow * PW + kcol]);
            const float* g = K + (size_t)((tile + 1) * 64 + krow) * HID + hoff + kcol;
            #pragma unroll
            for (int i = 0; i < 4; i++) CP_ASYNC16(d + i * 16, g + i * 4);
        }
        CP_COMMIT();
        __syncthreads();

        // S = Q K^T
        float s[8][4];
        #pragma unroll
        for (int nt = 0; nt < 8; nt++)
            #pragma unroll
            for (int i = 0; i < 4; i++) s[nt][i] = 0.0f;

        {
            const unsigned kbase = sptr(&KB[buf * 64 * PW + brr * PW + bcc]);
            #pragma unroll
            for (int g = 0; g < 8; g++) {
                #pragma unroll
                for (int ntp = 0; ntp < 4; ntp++) {
                    unsigned b0, b1, b2, b3;
                    ldsm4(b0, b1, b2, b3, kbase + (unsigned)(ntp * 16 * PW + g * 8) * 4);
                    unsigned ba[2] = {b0, b1}, bb[2] = {b2, b3};
                    mma8(s[2 * ntp],     qa[g], ba);
                    mma8(s[2 * ntp + 1], qa[g], bb);
                }
            }
        }

        // Online softmax (log2 domain)
        float mx0 = -1e30f, mx1 = -1e30f;
        #pragma unroll
        for (int nt = 0; nt < 8; nt++) {
            s[nt][0] *= SCL2; s[nt][1] *= SCL2;
            s[nt][2] *= SCL2; s[nt][3] *= SCL2;
            mx0 = fmaxf(mx0, fmaxf(s[nt][0], s[nt][1]));
            mx1 = fmaxf(mx1, fmaxf(s[nt][2], s[nt][3]));
        }
        mx0 = fmaxf(mx0, __shfl_xor_sync(0xffffffffu, mx0, 1));
        mx0 = fmaxf(mx0, __shfl_xor_sync(0xffffffffu, mx0, 2));
        mx1 = fmaxf(mx1, __shfl_xor_sync(0xffffffffu, mx1, 1));
        mx1 = fmaxf(mx1, __shfl_xor_sync(0xffffffffu, mx1, 2));

        float mn0 = fmaxf(mrow0, mx0);
        float mn1 = fmaxf(mrow1, mx1);
        float a0 = ex2f(mrow0 - mn0);
        float a1 = ex2f(mrow1 - mn1);

        {
            const int pr = lane >> 2;
            const int pc = 2 * (lane & 3);
            unsigned* P0 = &QP[(warp * 16 + pr) * PW + pc];
            unsigned* P1 = &QP[(warp * 16 + pr + 8) * PW + pc];
            float rs0 = 0.0f, rs1 = 0.0f;
            #pragma unroll
            for (int nt = 0; nt < 8; nt++) {
                float p0 = ex2f(s[nt][0] - mn0);
                float p1 = ex2f(s[nt][1] - mn0);
                float p2 = ex2f(s[nt][2] - mn1);
                float p3 = ex2f(s[nt][3] - mn1);
                rs0 += p0 + p1;
                rs1 += p2 + p3;
                uint2 w0 = {f2tf32(p0), f2tf32(p1)};
                uint2 w1 = {f2tf32(p2), f2tf32(p3)};
                *(uint2*)(P0 + nt * 8) = w0;
                *(uint2*)(P1 + nt * 8) = w1;
            }
            rs0 += __shfl_xor_sync(0xffffffffu, rs0, 1);
            rs0 += __shfl_xor_sync(0xffffffffu, rs0, 2);
            rs1 += __shfl_xor_sync(0xffffffffu, rs1, 1);
            rs1 += __shfl_xor_sync(0xffffffffu, rs1, 2);
            lrow0 = lrow0 * a0 + rs0;
            lrow1 = lrow1 * a1 + rs1;
            mrow0 = mn0; mrow1 = mn1;
        }
        #pragma unroll
        for (int nt = 0; nt < 8; nt++) {
            o[nt][0] *= a0; o[nt][1] *= a0;
            o[nt][2] *= a1; o[nt][3] *= a1;
        }
        __syncwarp();

        // O += P @ V
        {
            #pragma unroll
            for (int g = 0; g < 8; g++) {
                unsigned pa[4];
                ldsm4(pa[0], pa[1], pa[2], pa[3], pbase + g * 32);
                #pragma unroll
                for (int ntp = 0; ntp < 4; ntp++) {
                    int cc = (g * 8 + bcc) ^ (ntp << 2);
                    unsigned b0, b1, b2, b3;
                    ldsm4(b0, b1, b2, b3, vtbase + (unsigned)(ntp * 16 * PW + cc) * 4);
                    unsigned ba[2] = {b0, b1}, bb[2] = {b2, b3};
                    mma8(o[2 * ntp],     pa, ba);
                    mma8(o[2 * ntp + 1], pa, bb);
                }
            }
        }
    }

    // Write O (tf32-rounded; consumed as GEMM A operand)
    float i0 = 1.0f / lrow0;
    float i1 = 1.0f / lrow1;
    int r0 = q0 + warp * 16 + (lane >> 2);
    #pragma unroll
    for (int nt = 0; nt < 8; nt++) {
        int c = hoff + nt * 8 + 2 * (lane & 3);
        uint2 v0 = {f2tf32(o[nt][0] * i0), f2tf32(o[nt][1] * i0)};
        uint2 v1 = {f2tf32(o[nt][2] * i1), f2tf32(o[nt][3] * i1)};
        *(uint2*)&O[(size_t)r0 * HID + c] = v0;
        *(uint2*)&O[(size_t)(r0 + 8) * HID + c] = v1;
    }
}

// ---------------------------------------------------------------------------
// Combine: rec = 0.5*(a+b) in fp32 and tf32 copies
// ---------------------------------------------------------------------------
__global__ void combine_kernel(const float4* __restrict__ a,
                               const float4* __restrict__ b,
                               float4* __restrict__ oF,
                               float4* __restrict__ oT, int n4)
{
    int i = blockIdx.x * blockDim.x + threadIdx.x;
    if (i < n4) {
        float4 x = a[i], y = b[i], r;
        r.x = 0.5f * (x.x + y.x); r.y = 0.5f * (x.y + y.y);
        r.z = 0.5f * (x.z + y.z); r.w = 0.5f * (x.w + y.w);
        oF[i] = r;
        *(uint4*)&oT[i] = cvt4(r);
    }
}

// ---------------------------------------------------------------------------
// Launch
// ---------------------------------------------------------------------------
extern "C" void kernel_launch(void* const* d_in, const int* in_sizes, int n_in,
                              void* d_out, int out_size)
{
    (void)in_sizes; (void)n_in; (void)out_size;

    const float* hs   = (const float*)d_in[0];
    const float* past = (const float*)d_in[1];
    const float* Wq = (const float*)d_in[2];  const float* bq = (const float*)d_in[3];
    const float* Wk = (const float*)d_in[4];  const float* bk = (const float*)d_in[5];
    const float* Wv = (const float*)d_in[6];  const float* bv = (const float*)d_in[7];
    const float* Wo = (const float*)d_in[8];  const float* bo = (const float*)d_in[9];
    const float* Wrq = (const float*)d_in[10]; const float* brq = (const float*)d_in[11];
    const float* Wrk = (const float*)d_in[12]; const float* brk = (const float*)d_in[13];
    const float* Wrv = (const float*)d_in[14]; const float* brv = (const float*)d_in[15];
    const float* Wg = (const float*)d_in[16];  const float* bg = (const float*)d_in[17];

    float *wt, *hs_t, *past_t, *q, *k, *v, *ctx_t, *out, *out_t, *rq, *rk, *rv,
          *rctx, *rec, *rec_t;
    cudaGetSymbolAddress((void**)&wt,     g_wt);
    cudaGetSymbolAddress((void**)&hs_t,   g_hs_t);
    cudaGetSymbolAddress((void**)&past_t, g_past_t);
    cudaGetSymbolAddress((void**)&q,      g_q);
    cudaGetSymbolAddress((void**)&k,      g_k);
    cudaGetSymbolAddress((void**)&v,      g_v);
    cudaGetSymbolAddress((void**)&ctx_t,  g_ctx_t);
    cudaGetSymbolAddress((void**)&out,    g_out);
    cudaGetSymbolAddress((void**)&out_t,  g_out_t);
    cudaGetSymbolAddress((void**)&rq,     g_rq);
    cudaGetSymbolAddress((void**)&rk,     g_rk);
    cudaGetSymbolAddress((void**)&rv,     g_rv);
    cudaGetSymbolAddress((void**)&rctx,   g_rctx);
    cudaGetSymbolAddress((void**)&rec,    g_rec);
    cudaGetSymbolAddress((void**)&rec_t,  g_rec_t);

    cudaFuncSetAttribute(attn_t_kernel,
                         cudaFuncAttributeMaxDynamicSharedMemorySize, ATTN_SMEM);
    cudaFuncSetAttribute(gemm_tt_kernel,
                         cudaFuncAttributeMaxDynamicSharedMemorySize, GSMEM);
    cudaFuncSetAttribute(gemm_gate_kernel,
                         cudaFuncAttributeMaxDynamicSharedMemorySize, GSMEM);

    #define WT(i) (wt + (size_t)(i) * HID * HID)

    // --- prep: transpose+round weights, round activations ---
    {
        P9 ws = {{Wq, Wk, Wv, Wo, Wrq, Wrk, Wrv, Wg, Wg + (size_t)HID * HID}};
        prep_wt_kernel<<<dim3(32, 32, 9), 256>>>(ws, wt);
    }
    prep_rnd_kernel<<<SH / 4 / 256, 256>>>((const float4*)hs, (float4*)hs_t, SH / 4);
    prep_rnd_kernel<<<2 * SH / 4 / 256, 256>>>((const float4*)past, (float4*)past_t,
                                               2 * SH / 4);

    // --- self attention ---
    {
        GJ3 gj = {{{hs_t, WT(0), bq, q, 0, 1, 0},
                   {hs_t, WT(1), bk, k, 0, 1, 0},
                   {hs_t, WT(2), bv, v, 0, 1, 0}}};
        gemm_tt_kernel<<<dim3(8, 32, 3), 256, GSMEM>>>(gj, S_LEN, HID, HID);
    }
    attn_t_kernel<<<dim3(16, 16, 1), 256, ATTN_SMEM>>>(q, k, v, ctx_t);
    {
        GJ3 gj = {{{ctx_t, WT(3), bo, out, out_t, 0, 0}, {}, {}}};
        gemm_tt_kernel<<<dim3(8, 32, 1), 256, GSMEM>>>(gj, S_LEN, HID, HID);
    }

    // --- recursive attention ---
    {
        GJ3 gj = {{{out_t, WT(4), brq, rq, 0, 1, 0}, {}, {}}};
        gemm_tt_kernel<<<dim3(8, 32, 1), 256, GSMEM>>>(gj, S_LEN, HID, HID);
    }
    {
        GJ3 gj = {{{past_t, WT(5), brk, rk, 0, 1, 0},
                   {past_t, WT(6), brv, rv, 0, 1, 0}, {}}};
        gemm_tt_kernel<<<dim3(8, 64, 2), 256, GSMEM>>>(gj, 2 * S_LEN, HID, HID);
    }
    attn_t_kernel<<<dim3(16, 16, 2), 256, ATTN_SMEM>>>(rq, rk, rv, rctx);
    combine_kernel<<<SH / 4 / 256, 256>>>((const float4*)rctx,
                                          (const float4*)(rctx + SH),
                                          (float4*)rec, (float4*)rec_t, SH / 4);

    // --- fused gate + blend -> d_out ---
    gemm_gate_kernel<<<dim3(8, 32), 256, GSMEM>>>(out_t, rec_t, WT(7), WT(8), bg,
                                                  out, rec, (float*)d_out, HID);
}

// round 7
// speedup vs baseline: 1.0295x; 1.0295x over previous
#include <cuda_runtime.h>
#include <math.h>
#include <stdint.h>

// Problem constants
#define S_LEN 2048
#define HID   1024
#define NHEAD 16
#define HDIM  64
#define SH    (S_LEN * HID)
#define SCL2  0.1803368801111204f   // (1/sqrt(64)) * log2(e)
#define LOG2E 1.4426950408889634f

// ---------------------------------------------------------------------------
// Scratch
// ---------------------------------------------------------------------------
__device__ float g_wt[9 * HID * HID];   // 9 transposed tf32 weights [n][k]
__device__ float g_hs_t[SH];
__device__ float g_past_t[2 * SH];
__device__ float g_q[SH];
__device__ float g_k[SH];
__device__ float g_v[SH];
__device__ float g_ctx_t[SH];
__device__ float g_out[SH];
__device__ float g_out_t[SH];
__device__ float g_rq[SH];
__device__ float g_rk[2 * SH];
__device__ float g_rv[2 * SH];
__device__ float g_rctx[2 * SH];
__device__ float g_rec[SH];
__device__ float g_rec_t[SH];

// ---------------------------------------------------------------------------
// helpers
// ---------------------------------------------------------------------------
__device__ __forceinline__ unsigned f2tf32(float x) {
    unsigned r;
    asm("cvt.rna.tf32.f32 %0, %1;" : "=r"(r) : "f"(x));
    return r;
}
__device__ __forceinline__ uint4 cvt4(float4 v) {
    uint4 r;
    r.x = f2tf32(v.x); r.y = f2tf32(v.y);
    r.z = f2tf32(v.z); r.w = f2tf32(v.w);
    return r;
}
__device__ __forceinline__ void mma8(float* c, const unsigned* a, const unsigned* b) {
    asm volatile(
        "mma.sync.aligned.m16n8k8.row.col.f32.tf32.tf32.f32 "
        "{%0,%1,%2,%3}, {%4,%5,%6,%7}, {%8,%9}, {%0,%1,%2,%3};\n"
        : "+f"(c[0]), "+f"(c[1]), "+f"(c[2]), "+f"(c[3])
        : "r"(a[0]), "r"(a[1]), "r"(a[2]), "r"(a[3]), "r"(b[0]), "r"(b[1]));
}
__device__ __forceinline__ void ldsm4(unsigned &r0, unsigned &r1,
                                      unsigned &r2, unsigned &r3, unsigned a) {
    asm volatile("ldmatrix.sync.aligned.m8n8.x4.shared.b16 {%0,%1,%2,%3}, [%4];"
        : "=r"(r0), "=r"(r1), "=r"(r2), "=r"(r3) : "r"(a));
}
__device__ __forceinline__ unsigned sptr(const void* p) {
    return (unsigned)__cvta_generic_to_shared(p);
}
__device__ __forceinline__ float ex2f(float x) {
    float y; asm("ex2.approx.ftz.f32 %0, %1;" : "=f"(y) : "f"(x)); return y;
}
#define CP_ASYNC16(dst, src) \
    asm volatile("cp.async.cg.shared.global [%0], [%1], 16;" :: "r"(dst), "l"(src) : "memory")
#define CP_COMMIT() asm volatile("cp.async.commit_group;" ::: "memory")
#define CP_WAIT0()  asm volatile("cp.async.wait_group 0;" ::: "memory")
#define CP_WAIT1()  asm volatile("cp.async.wait_group 1;" ::: "memory")

// ---------------------------------------------------------------------------
// Prep kernels
// ---------------------------------------------------------------------------
struct P9 { const float* p[9]; };

__global__ void __launch_bounds__(256) prep_wt_kernel(P9 ws, float* __restrict__ dst)
{
    __shared__ float t[32][33];
    const float* __restrict__ src = ws.p[blockIdx.z];
    float* __restrict__ d = dst + (size_t)blockIdx.z * HID * HID;
    const int r0 = blockIdx.y * 32, c0 = blockIdx.x * 32;
    const int lr = threadIdx.x >> 3, lc = (threadIdx.x & 7) * 4;

    float4 v = *(const float4*)&src[(size_t)(r0 + lr) * HID + c0 + lc];
    t[lr][lc] = v.x; t[lr][lc + 1] = v.y; t[lr][lc + 2] = v.z; t[lr][lc + 3] = v.w;
    __syncthreads();

    uint4 w;
    w.x = f2tf32(t[lc + 0][lr]);
    w.y = f2tf32(t[lc + 1][lr]);
    w.z = f2tf32(t[lc + 2][lr]);
    w.w = f2tf32(t[lc + 3][lr]);
    *(uint4*)&d[(size_t)(c0 + lr) * HID + r0 + lc] = w;
}

__global__ void prep_rnd_kernel(const float4* __restrict__ s,
                                float4* __restrict__ d, int n4)
{
    int i = blockIdx.x * blockDim.x + threadIdx.x;
    if (i < n4) *(uint4*)&d[i] = cvt4(s[i]);
}

// ---------------------------------------------------------------------------
// GEMM: C[M,N] = A[M,K] @ Bt[N,K]^T + bias. 128x128 tile, BK=32, 8 warps
// (warp tile 64x32). 3-stage cp.async ring (2 loads in flight), ldmatrix
// fragments. All operands pre-rounded tf32.
// ---------------------------------------------------------------------------
#define TPX 36
#define STG_WORDS ((128 + 128) * TPX)      // words per stage
#define GSMEM3 (3 * STG_WORDS * 4)

struct GJob { const float* A; const float* Bt; const float* bias;
              float* C; float* C2; int rnd; int pad; };
struct GJ3 { GJob j[3]; };

__global__ void __launch_bounds__(256, 2) gemm_tt_kernel(GJ3 gj, int M, int N, int K)
{
    extern __shared__ unsigned sm[];
    const GJob jb = gj.j[blockIdx.z];

    const int tid  = threadIdx.x;
    const int warp = tid >> 5;
    const int lane = tid & 31;
    const int m0 = blockIdx.y * 128;
    const int n0 = blockIdx.x * 128;
    const int wm0 = (warp >> 2) * 64;     // 0 or 64
    const int wn0 = (warp & 3) * 32;      // 0..96

    // staging: row = tid>>1 (0..127), col = (tid&1)*16 floats (4 x 16B)
    const int srow = tid >> 1;
    const int scol = (tid & 1) * 16;
    const float* Ag = jb.A  + (size_t)(m0 + srow) * K + scol;
    const float* Bg = jb.Bt + (size_t)(n0 + srow) * K + scol;
    const unsigned smb = sptr(sm);
    const unsigned sa = smb + (srow * TPX + scol) * 4;
    const unsigned sb = smb + (128 * TPX + srow * TPX + scol) * 4;

    // ldmatrix lane decomposition
    const int lr  = (lane & 7) + ((lane >> 3) & 1) * 8;
    const int lc  = ((lane >> 4) & 1) * 4;
    const int brr = ((lane >> 4) & 1) * 8 + (lane & 7);
    const int bcc = ((lane >> 3) & 1) * 4;

    float acc[4][4][4];
    #pragma unroll
    for (int mt = 0; mt < 4; mt++)
        #pragma unroll
        for (int nt = 0; nt < 4; nt++)
            #pragma unroll
            for (int i = 0; i < 4; i++) acc[mt][nt][i] = 0.0f;

    const int T = K / 32;
    auto issue = [&](int st) {
        if (st < T) {
            const unsigned off = (unsigned)((st % 3) * STG_WORDS) * 4;
            const int ko = st * 32;
            #pragma unroll
            for (int i = 0; i < 4; i++) CP_ASYNC16(sa + off + i * 16, Ag + ko + i * 4);
            #pragma unroll
            for (int i = 0; i < 4; i++) CP_ASYNC16(sb + off + i * 16, Bg + ko + i * 4);
        }
        CP_COMMIT();
    };

    issue(0);
    issue(1);

    for (int t = 0; t < T; t++) {
        CP_WAIT1();
        __syncthreads();
        issue(t + 2);

        const unsigned so = (unsigned)((t % 3) * STG_WORDS);
        const unsigned ab = smb + (so + (wm0 + lr) * TPX + lc) * 4;
        const unsigned bb = smb + (so + 128 * TPX + (wn0 + brr) * TPX + bcc) * 4;
        #pragma unroll
        for (int ks = 0; ks < 4; ks++) {
            unsigned a[4][4];
            #pragma unroll
            for (int mt = 0; mt < 4; mt++)
                ldsm4(a[mt][0], a[mt][1], a[mt][2], a[mt][3],
                      ab + (unsigned)(mt * 16 * TPX + ks * 8) * 4);
            #pragma unroll
            for (int ntp = 0; ntp < 2; ntp++) {
                unsigned b0, b1, b2, b3;
                ldsm4(b0, b1, b2, b3, bb + (unsigned)(ntp * 16 * TPX + ks * 8) * 4);
                unsigned ba[2] = {b0, b1}, bx[2] = {b2, b3};
                #pragma unroll
                for (int mt = 0; mt < 4; mt++) {
                    mma8(acc[mt][2 * ntp],     a[mt], ba);
                    mma8(acc[mt][2 * ntp + 1], a[mt], bx);
                }
            }
        }
        __syncthreads();
    }

    #pragma unroll
    for (int mt = 0; mt < 4; mt++) {
        #pragma unroll
        for (int nt = 0; nt < 4; nt++) {
            int r0 = m0 + wm0 + mt * 16 + (lane >> 2);
            int c0 = n0 + wn0 + nt * 8 + 2 * (lane & 3);
            float b0 = jb.bias[c0], b1 = jb.bias[c0 + 1];
            float v0 = acc[mt][nt][0] + b0, v1 = acc[mt][nt][1] + b1;
            float v2 = acc[mt][nt][2] + b0, v3 = acc[mt][nt][3] + b1;
            size_t p0 = (size_t)r0 * N + c0;
            size_t p1 = (size_t)(r0 + 8) * N + c0;
            if (jb.C2) {
                uint2 u0 = {f2tf32(v0), f2tf32(v1)};
                uint2 u1 = {f2tf32(v2), f2tf32(v3)};
                *(uint2*)&jb.C2[p0] = u0;
                *(uint2*)&jb.C2[p1] = u1;
            }
            if (jb.rnd) {
                v0 = __uint_as_float(f2tf32(v0));
                v1 = __uint_as_float(f2tf32(v1));
                v2 = __uint_as_float(f2tf32(v2));
                v3 = __uint_as_float(f2tf32(v3));
            }
            float2 w0 = {v0, v1}, w1 = {v2, v3};
            *(float2*)&jb.C[p0] = w0;
            *(float2*)&jb.C[p1] = w1;
        }
    }
}

// ---------------------------------------------------------------------------
// Fused gate GEMM: gpre = [out_t|rec_t] @ WgT^T + bg (K=2048), then
// dst = out + sigmoid(gpre) * (rec - out). Same 128x128 3-stage pipeline.
// ---------------------------------------------------------------------------
__global__ void __launch_bounds__(256, 2) gemm_gate_kernel(
    const float* __restrict__ outT, const float* __restrict__ recT,
    const float* __restrict__ WgT_lo, const float* __restrict__ WgT_hi,
    const float* __restrict__ bias,
    const float* __restrict__ outF, const float* __restrict__ recF,
    float* __restrict__ dst, int N)
{
    extern __shared__ unsigned sm[];

    const int tid  = threadIdx.x;
    const int warp = tid >> 5;
    const int lane = tid & 31;
    const int m0 = blockIdx.y * 128;
    const int n0 = blockIdx.x * 128;
    const int wm0 = (warp >> 2) * 64;
    const int wn0 = (warp & 3) * 32;

    const int srow = tid >> 1;
    const int scol = (tid & 1) * 16;
    const size_t aoff = (size_t)(m0 + srow) * HID + scol;
    const size_t boff = (size_t)(n0 + srow) * HID + scol;
    const unsigned smb = sptr(sm);
    const unsigned sa = smb + (srow * TPX + scol) * 4;
    const unsigned sb = smb + (128 * TPX + srow * TPX + scol) * 4;

    const int lr  = (lane & 7) + ((lane >> 3) & 1) * 8;
    const int lc  = ((lane >> 4) & 1) * 4;
    const int brr = ((lane >> 4) & 1) * 8 + (lane & 7);
    const int bcc = ((lane >> 3) & 1) * 4;

    float acc[4][4][4];
    #pragma unroll
    for (int mt = 0; mt < 4; mt++)
        #pragma unroll
        for (int nt = 0; nt < 4; nt++)
            #pragma unroll
            for (int i = 0; i < 4; i++) acc[mt][nt][i] = 0.0f;

    const int T = (2 * HID) / 32;
    auto issue = [&](int st) {
        if (st < T) {
            const unsigned off = (unsigned)((st % 3) * STG_WORDS) * 4;
            const int kn = st * 32;
            const int ka = kn & (HID - 1);
            const float* As_ = (kn < HID) ? outT : recT;
            const float* Bs_ = (kn < HID) ? WgT_lo : WgT_hi;
            #pragma unroll
            for (int i = 0; i < 4; i++) CP_ASYNC16(sa + off + i * 16, As_ + aoff + ka + i * 4);
            #pragma unroll
            for (int i = 0; i < 4; i++) CP_ASYNC16(sb + off + i * 16, Bs_ + boff + ka + i * 4);
        }
        CP_COMMIT();
    };

    issue(0);
    issue(1);

    for (int t = 0; t < T; t++) {
        CP_WAIT1();
        __syncthreads();
        issue(t + 2);

        const unsigned so = (unsigned)((t % 3) * STG_WORDS);
        const unsigned ab = smb + (so + (wm0 + lr) * TPX + lc) * 4;
        const unsigned bb = smb + (so + 128 * TPX + (wn0 + brr) * TPX + bcc) * 4;
        #pragma unroll
        for (int ks = 0; ks < 4; ks++) {
            unsigned a[4][4];
            #pragma unroll
            for (int mt = 0; mt < 4; mt++)
                ldsm4(a[mt][0], a[mt][1], a[mt][2], a[mt][3],
                      ab + (unsigned)(mt * 16 * TPX + ks * 8) * 4);
            #pragma unroll
            for (int ntp = 0; ntp < 2; ntp++) {
                unsigned b0, b1, b2, b3;
                ldsm4(b0, b1, b2, b3, bb + (unsigned)(ntp * 16 * TPX + ks * 8) * 4);
                unsigned ba[2] = {b0, b1}, bx[2] = {b2, b3};
                #pragma unroll
                for (int mt = 0; mt < 4; mt++) {
                    mma8(acc[mt][2 * ntp],     a[mt], ba);
                    mma8(acc[mt][2 * ntp + 1], a[mt], bx);
                }
            }
        }
        __syncthreads();
    }

    #pragma unroll
    for (int mt = 0; mt < 4; mt++) {
        #pragma unroll
        for (int nt = 0; nt < 4; nt++) {
            int r0 = m0 + wm0 + mt * 16 + (lane >> 2);
            int c0 = n0 + wn0 + nt * 8 + 2 * (lane & 3);
            float b0 = bias[c0], b1 = bias[c0 + 1];
            float gp0 = acc[mt][nt][0] + b0, gp1 = acc[mt][nt][1] + b1;
            float gp2 = acc[mt][nt][2] + b0, gp3 = acc[mt][nt][3] + b1;
            size_t p0 = (size_t)r0 * N + c0;
            size_t p1 = (size_t)(r0 + 8) * N + c0;
            float2 o0 = *(const float2*)&outF[p0];
            float2 o1 = *(const float2*)&outF[p1];
            float2 rc0 = *(const float2*)&recF[p0];
            float2 rc1 = *(const float2*)&recF[p1];
            float gg0 = 1.0f / (1.0f + ex2f(-gp0 * LOG2E));
            float gg1 = 1.0f / (1.0f + ex2f(-gp1 * LOG2E));
            float gg2 = 1.0f / (1.0f + ex2f(-gp2 * LOG2E));
            float gg3 = 1.0f / (1.0f + ex2f(-gp3 * LOG2E));
            float2 w0 = {o0.x + gg0 * (rc0.x - o0.x), o0.y + gg1 * (rc0.y - o0.y)};
            float2 w1 = {o1.x + gg2 * (rc1.x - o1.x), o1.y + gg3 * (rc1.y - o1.y)};
            *(float2*)&dst[p0] = w0;
            *(float2*)&dst[p1] = w1;
        }
    }
}

// ---------------------------------------------------------------------------
// Flash attention (unchanged from round 6)
// ---------------------------------------------------------------------------
#define PW 68
#define ATTN_WORDS ((128 + 2 * 64 + 64) * PW)
#define ATTN_SMEM  (ATTN_WORDS * 4)

__global__ void __launch_bounds__(256, 2) attn_t_kernel(
    const float* __restrict__ Q, const float* __restrict__ K,
    const float* __restrict__ V, float* __restrict__ O)
{
    extern __shared__ unsigned sm[];
    unsigned* QP = sm;
    unsigned* KB = sm + 128 * PW;
    unsigned* VT = sm + (128 + 128) * PW;

    const size_t zoff = (size_t)blockIdx.z * SH;
    K += zoff; V += zoff; O += zoff;

    const int tid  = threadIdx.x;
    const int warp = tid >> 5;
    const int lane = tid & 31;
    const int hoff = blockIdx.y * HDIM;
    const int q0   = blockIdx.x * 128;

    const int lr  = (lane & 7) + ((lane >> 3) & 1) * 8;
    const int lc  = ((lane >> 4) & 1) * 4;
    const int brr = ((lane >> 4) & 1) * 8 + (lane & 7);
    const int bcc = ((lane >> 3) & 1) * 4;

    const int krow = tid >> 2;
    const int kcol = (tid & 3) * 16;

    {
        const int row = tid >> 1, half = tid & 1;
        const uint4* Qg = (const uint4*)(Q + (size_t)(q0 + row) * HID + hoff) + half * 8;
        uint4* Qs = (uint4*)&QP[row * PW + half * 32];
        #pragma unroll
        for (int j = 0; j < 8; j++) Qs[j] = Qg[j];
    }

    {
        unsigned d = sptr(&KB[krow * PW + kcol]);
        const float* g = K + (size_t)krow * HID + hoff + kcol;
        #pragma unroll
        for (int i = 0; i < 4; i++) CP_ASYNC16(d + i * 16, g + i * 4);
        CP_COMMIT();
    }
    __syncthreads();

    unsigned qa[8][4];
    {
        unsigned base = sptr(&QP[(warp * 16 + lr) * PW + lc]);
        #pragma unroll
        for (int g = 0; g < 8; g++)
            ldsm4(qa[g][0], qa[g][1], qa[g][2], qa[g][3], base + g * 32);
    }

    float o[8][4];
    #pragma unroll
    for (int nt = 0; nt < 8; nt++)
        #pragma unroll
        for (int i = 0; i < 4; i++) o[nt][i] = 0.0f;
    float mrow0 = -1e30f, mrow1 = -1e30f, lrow0 = 0.0f, lrow1 = 0.0f;

    const unsigned pbase  = sptr(&QP[(warp * 16 + lr) * PW + lc]);
    const unsigned vtbase = sptr(&VT[brr * PW]);
    const int vswz = (tid & 3) << 2;

    for (int tile = 0; tile < S_LEN / 64; tile++) {
        const int buf = tile & 1;

        uint4 vr[4];
        {
            const uint4* Vg = (const uint4*)(V + (size_t)(tile * 64 + krow) * HID + hoff + kcol);
            #pragma unroll
            for (int i = 0; i < 4; i++) vr[i] = Vg[i];
        }

        CP_WAIT0();
        __syncthreads();

        {
            const int col = krow ^ vswz;
            #pragma unroll
            for (int i = 0; i < 16; i++) {
                int d = (tid & 3) * 16 + i;
                VT[d * PW + col] = ((const unsigned*)vr)[i];
            }
        }

        if (tile + 1 < S_LEN / 64) {
            unsigned d = sptr(&KB[(buf ^ 1) * 64 * PW + krow * PW + kcol]);
            const float* g = K + (size_t)((tile + 1) * 64 + krow) * HID + hoff + kcol;
            #pragma unroll
            for (int i = 0; i < 4; i++) CP_ASYNC16(d + i * 16, g + i * 4);
        }
        CP_COMMIT();
        __syncthreads();

        float s[8][4];
        #pragma unroll
        for (int nt = 0; nt < 8; nt++)
            #pragma unroll
            for (int i = 0; i < 4; i++) s[nt][i] = 0.0f;

        {
            const unsigned kbase = sptr(&KB[buf * 64 * PW + brr * PW + bcc]);
            #pragma unroll
            for (int g = 0; g < 8; g++) {
                #pragma unroll
                for (int ntp = 0; ntp < 4; ntp++) {
                    unsigned b0, b1, b2, b3;
                    ldsm4(b0, b1, b2, b3, kbase + (unsigned)(ntp * 16 * PW + g * 8) * 4);
                    unsigned ba[2] = {b0, b1}, bb[2] = {b2, b3};
                    mma8(s[2 * ntp],     qa[g], ba);
                    mma8(s[2 * ntp + 1], qa[g], bb);
                }
            }
        }

        float mx0 = -1e30f, mx1 = -1e30f;
        #pragma unroll
        for (int nt = 0; nt < 8; nt++) {
            s[nt][0] *= SCL2; s[nt][1] *= SCL2;
            s[nt][2] *= SCL2; s[nt][3] *= SCL2;
            mx0 = fmaxf(mx0, fmaxf(s[nt][0], s[nt][1]));
            mx1 = fmaxf(mx1, fmaxf(s[nt][2], s[nt][3]));
        }
        mx0 = fmaxf(mx0, __shfl_xor_sync(0xffffffffu, mx0, 1));
        mx0 = fmaxf(mx0, __shfl_xor_sync(0xffffffffu, mx0, 2));
        mx1 = fmaxf(mx1, __shfl_xor_sync(0xffffffffu, mx1, 1));
        mx1 = fmaxf(mx1, __shfl_xor_sync(0xffffffffu, mx1, 2));

        float mn0 = fmaxf(mrow0, mx0);
        float mn1 = fmaxf(mrow1, mx1);
        float a0 = ex2f(mrow0 - mn0);
        float a1 = ex2f(mrow1 - mn1);

        {
            const int pr = lane >> 2;
            const int pc = 2 * (lane & 3);
            unsigned* P0 = &QP[(warp * 16 + pr) * PW + pc];
            unsigned* P1 = &QP[(warp * 16 + pr + 8) * PW + pc];
            float rs0 = 0.0f, rs1 = 0.0f;
            #pragma unroll
            for (int nt = 0; nt < 8; nt++) {
                float p0 = ex2f(s[nt][0] - mn0);
                float p1 = ex2f(s[nt][1] - mn0);
                float p2 = ex2f(s[nt][2] - mn1);
                float p3 = ex2f(s[nt][3] - mn1);
                rs0 += p0 + p1;
                rs1 += p2 + p3;
                uint2 w0 = {f2tf32(p0), f2tf32(p1)};
                uint2 w1 = {f2tf32(p2), f2tf32(p3)};
                *(uint2*)(P0 + nt * 8) = w0;
                *(uint2*)(P1 + nt * 8) = w1;
            }
            rs0 += __shfl_xor_sync(0xffffffffu, rs0, 1);
            rs0 += __shfl_xor_sync(0xffffffffu, rs0, 2);
            rs1 += __shfl_xor_sync(0xffffffffu, rs1, 1);
            rs1 += __shfl_xor_sync(0xffffffffu, rs1, 2);
            lrow0 = lrow0 * a0 + rs0;
            lrow1 = lrow1 * a1 + rs1;
            mrow0 = mn0; mrow1 = mn1;
        }
        #pragma unroll
        for (int nt = 0; nt < 8; nt++) {
            o[nt][0] *= a0; o[nt][1] *= a0;
            o[nt][2] *= a1; o[nt][3] *= a1;
        }
        __syncwarp();

        {
            #pragma unroll
            for (int g = 0; g < 8; g++) {
                unsigned pa[4];
                ldsm4(pa[0], pa[1], pa[2], pa[3], pbase + g * 32);
                #pragma unroll
                for (int ntp = 0; ntp < 4; ntp++) {
                    int cc = (g * 8 + bcc) ^ (ntp << 2);
                    unsigned b0, b1, b2, b3;
                    ldsm4(b0, b1, b2, b3, vtbase + (unsigned)(ntp * 16 * PW + cc) * 4);
                    unsigned ba[2] = {b0, b1}, bb[2] = {b2, b3};
                    mma8(o[2 * ntp],     pa, ba);
                    mma8(o[2 * ntp + 1], pa, bb);
                }
            }
        }
    }

    float i0 = 1.0f / lrow0;
    float i1 = 1.0f / lrow1;
    int r0 = q0 + warp * 16 + (lane >> 2);
    #pragma unroll
    for (int nt = 0; nt < 8; nt++) {
        int c = hoff + nt * 8 + 2 * (lane & 3);
        uint2 v0 = {f2tf32(o[nt][0] * i0), f2tf32(o[nt][1] * i0)};
        uint2 v1 = {f2tf32(o[nt][2] * i1), f2tf32(o[nt][3] * i1)};
        *(uint2*)&O[(size_t)r0 * HID + c] = v0;
        *(uint2*)&O[(size_t)(r0 + 8) * HID + c] = v1;
    }
}

// ---------------------------------------------------------------------------
// Combine: rec = 0.5*(a+b) in fp32 and tf32 copies
// ---------------------------------------------------------------------------
__global__ void combine_kernel(const float4* __restrict__ a,
                               const float4* __restrict__ b,
                               float4* __restrict__ oF,
                               float4* __restrict__ oT, int n4)
{
    int i = blockIdx.x * blockDim.x + threadIdx.x;
    if (i < n4) {
        float4 x = a[i], y = b[i], r;
        r.x = 0.5f * (x.x + y.x); r.y = 0.5f * (x.y + y.y);
        r.z = 0.5f * (x.z + y.z); r.w = 0.5f * (x.w + y.w);
        oF[i] = r;
        *(uint4*)&oT[i] = cvt4(r);
    }
}

// ---------------------------------------------------------------------------
// Launch
// ---------------------------------------------------------------------------
extern "C" void kernel_launch(void* const* d_in, const int* in_sizes, int n_in,
                              void* d_out, int out_size)
{
    (void)in_sizes; (void)n_in; (void)out_size;

    const float* hs   = (const float*)d_in[0];
    const float* past = (const float*)d_in[1];
    const float* Wq = (const float*)d_in[2];  const float* bq = (const float*)d_in[3];
    const float* Wk = (const float*)d_in[4];  const float* bk = (const float*)d_in[5];
    const float* Wv = (const float*)d_in[6];  const float* bv = (const float*)d_in[7];
    const float* Wo = (const float*)d_in[8];  const float* bo = (const float*)d_in[9];
    const float* Wrq = (const float*)d_in[10]; const float* brq = (const float*)d_in[11];
    const float* Wrk = (const float*)d_in[12]; const float* brk = (const float*)d_in[13];
    const float* Wrv = (const float*)d_in[14]; const float* brv = (const float*)d_in[15];
    const float* Wg = (const float*)d_in[16];  const float* bg = (const float*)d_in[17];

    float *wt, *hs_t, *past_t, *q, *k, *v, *ctx_t, *out, *out_t, *rq, *rk, *rv,
          *rctx, *rec, *rec_t;
    cudaGetSymbolAddress((void**)&wt,     g_wt);
    cudaGetSymbolAddress((void**)&hs_t,   g_hs_t);
    cudaGetSymbolAddress((void**)&past_t, g_past_t);
    cudaGetSymbolAddress((void**)&q,      g_q);
    cudaGetSymbolAddress((void**)&k,      g_k);
    cudaGetSymbolAddress((void**)&v,      g_v);
    cudaGetSymbolAddress((void**)&ctx_t,  g_ctx_t);
    cudaGetSymbolAddress((void**)&out,    g_out);
    cudaGetSymbolAddress((void**)&out_t,  g_out_t);
    cudaGetSymbolAddress((void**)&rq,     g_rq);
    cudaGetSymbolAddress((void**)&rk,     g_rk);
    cudaGetSymbolAddress((void**)&rv,     g_rv);
    cudaGetSymbolAddress((void**)&rctx,   g_rctx);
    cudaGetSymbolAddress((void**)&rec,    g_rec);
    cudaGetSymbolAddress((void**)&rec_t,  g_rec_t);

    cudaFuncSetAttribute(attn_t_kernel,
                         cudaFuncAttributeMaxDynamicSharedMemorySize, ATTN_SMEM);
    cudaFuncSetAttribute(gemm_tt_kernel,
                         cudaFuncAttributeMaxDynamicSharedMemorySize, GSMEM3);
    cudaFuncSetAttribute(gemm_gate_kernel,
                         cudaFuncAttributeMaxDynamicSharedMemorySize, GSMEM3);

    #define WT(i) (wt + (size_t)(i) * HID * HID)

    // --- prep ---
    {
        P9 ws = {{Wq, Wk, Wv, Wo, Wrq, Wrk, Wrv, Wg, Wg + (size_t)HID * HID}};
        prep_wt_kernel<<<dim3(32, 32, 9), 256>>>(ws, wt);
    }
    prep_rnd_kernel<<<SH / 4 / 256, 256>>>((const float4*)hs, (float4*)hs_t, SH / 4);
    prep_rnd_kernel<<<2 * SH / 4 / 256, 256>>>((const float4*)past, (float4*)past_t,
                                               2 * SH / 4);

    // --- self attention ---
    {
        GJ3 gj = {{{hs_t, WT(0), bq, q, 0, 1, 0},
                   {hs_t, WT(1), bk, k, 0, 1, 0},
                   {hs_t, WT(2), bv, v, 0, 1, 0}}};
        gemm_tt_kernel<<<dim3(8, 16, 3), 256, GSMEM3>>>(gj, S_LEN, HID, HID);
    }
    attn_t_kernel<<<dim3(16, 16, 1), 256, ATTN_SMEM>>>(q, k, v, ctx_t);
    {
        GJ3 gj = {{{ctx_t, WT(3), bo, out, out_t, 0, 0}, {}, {}}};
        gemm_tt_kernel<<<dim3(8, 16, 1), 256, GSMEM3>>>(gj, S_LEN, HID, HID);
    }

    // --- recursive attention ---
    {
        GJ3 gj = {{{out_t, WT(4), brq, rq, 0, 1, 0}, {}, {}}};
        gemm_tt_kernel<<<dim3(8, 16, 1), 256, GSMEM3>>>(gj, S_LEN, HID, HID);
    }
    {
        GJ3 gj = {{{past_t, WT(5), brk, rk, 0, 1, 0},
                   {past_t, WT(6), brv, rv, 0, 1, 0}, {}}};
        gemm_tt_kernel<<<dim3(8, 32, 2), 256, GSMEM3>>>(gj, 2 * S_LEN, HID, HID);
    }
    attn_t_kernel<<<dim3(16, 16, 2), 256, ATTN_SMEM>>>(rq, rk, rv, rctx);
    combine_kernel<<<SH / 4 / 256, 256>>>((const float4*)rctx,
                                          (const float4*)(rctx + SH),
                                          (float4*)rec, (float4*)rec_t, SH / 4);

    // --- fused gate + blend -> d_out ---
    gemm_gate_kernel<<<dim3(8, 16), 256, GSMEM3>>>(out_t, rec_t, WT(7), WT(8), bg,
                                                   out, rec, (float*)d_out, HID);
}

// round 9
// speedup vs baseline: 1.0932x; 1.0619x over previous
#include <cuda_runtime.h>
#include <math.h>
#include <stdint.h>

// Problem constants
#define S_LEN 2048
#define HID   1024
#define NHEAD 16
#define HDIM  64
#define SH    (S_LEN * HID)
#define SCL2  0.1803368801111204f   // (1/sqrt(64)) * log2(e)
#define LOG2E 1.4426950408889634f

// ---------------------------------------------------------------------------
// Scratch
// ---------------------------------------------------------------------------
__device__ float g_wt[9 * HID * HID];   // 9 transposed tf32 weights [n][k]
__device__ float g_hs_t[SH];
__device__ float g_past_t[2 * SH];
__device__ float g_q[SH];
__device__ float g_k[SH];
__device__ float g_v[SH];
__device__ float g_ctx_t[SH];
__device__ float g_out[SH];
__device__ float g_out_t[SH];
__device__ float g_rq[SH];
__device__ float g_rk[2 * SH];
__device__ float g_rv[2 * SH];
__device__ float g_rctx[2 * SH];
__device__ float g_rec[SH];
__device__ float g_rec_t[SH];

// ---------------------------------------------------------------------------
// helpers
// ---------------------------------------------------------------------------
__device__ __forceinline__ unsigned f2tf32(float x) {
    unsigned r;
    asm("cvt.rna.tf32.f32 %0, %1;" : "=r"(r) : "f"(x));
    return r;
}
__device__ __forceinline__ uint4 cvt4(float4 v) {
    uint4 r;
    r.x = f2tf32(v.x); r.y = f2tf32(v.y);
    r.z = f2tf32(v.z); r.w = f2tf32(v.w);
    return r;
}
__device__ __forceinline__ void mma8(float* c, const unsigned* a, const unsigned* b) {
    asm volatile(
        "mma.sync.aligned.m16n8k8.row.col.f32.tf32.tf32.f32 "
        "{%0,%1,%2,%3}, {%4,%5,%6,%7}, {%8,%9}, {%0,%1,%2,%3};\n"
        : "+f"(c[0]), "+f"(c[1]), "+f"(c[2]), "+f"(c[3])
        : "r"(a[0]), "r"(a[1]), "r"(a[2]), "r"(a[3]), "r"(b[0]), "r"(b[1]));
}
__device__ __forceinline__ void ldsm4(unsigned &r0, unsigned &r1,
                                      unsigned &r2, unsigned &r3, unsigned a) {
    asm volatile("ldmatrix.sync.aligned.m8n8.x4.shared.b16 {%0,%1,%2,%3}, [%4];"
        : "=r"(r0), "=r"(r1), "=r"(r2), "=r"(r3) : "r"(a));
}
__device__ __forceinline__ unsigned sptr(const void* p) {
    return (unsigned)__cvta_generic_to_shared(p);
}
__device__ __forceinline__ float ex2f(float x) {
    float y; asm("ex2.approx.ftz.f32 %0, %1;" : "=f"(y) : "f"(x)); return y;
}
#define CP_ASYNC16(dst, src) \
    asm volatile("cp.async.cg.shared.global [%0], [%1], 16;" :: "r"(dst), "l"(src) : "memory")
#define CP_COMMIT() asm volatile("cp.async.commit_group;" ::: "memory")
#define CP_WAIT0()  asm volatile("cp.async.wait_group 0;" ::: "memory")
#define CP_WAIT1()  asm volatile("cp.async.wait_group 1;" ::: "memory")

// ---------------------------------------------------------------------------
// Prep kernels
// ---------------------------------------------------------------------------
struct P9 { const float* p[9]; };

__global__ void __launch_bounds__(256) prep_wt_kernel(P9 ws, float* __restrict__ dst)
{
    __shared__ float t[32][33];
    const float* __restrict__ src = ws.p[blockIdx.z];
    float* __restrict__ d = dst + (size_t)blockIdx.z * HID * HID;
    const int r0 = blockIdx.y * 32, c0 = blockIdx.x * 32;
    const int lr = threadIdx.x >> 3, lc = (threadIdx.x & 7) * 4;

    float4 v = *(const float4*)&src[(size_t)(r0 + lr) * HID + c0 + lc];
    t[lr][lc] = v.x; t[lr][lc + 1] = v.y; t[lr][lc + 2] = v.z; t[lr][lc + 3] = v.w;
    __syncthreads();

    uint4 w;
    w.x = f2tf32(t[lc + 0][lr]);
    w.y = f2tf32(t[lc + 1][lr]);
    w.z = f2tf32(t[lc + 2][lr]);
    w.w = f2tf32(t[lc + 3][lr]);
    *(uint4*)&d[(size_t)(c0 + lr) * HID + r0 + lc] = w;
}

__global__ void prep_rnd_kernel(const float4* __restrict__ s,
                                float4* __restrict__ d, int n4)
{
    int i = blockIdx.x * blockDim.x + threadIdx.x;
    if (i < n4) *(uint4*)&d[i] = cvt4(s[i]);
}

// ---------------------------------------------------------------------------
// GEMM: C[M,N] = A[M,K] @ Bt[N,K]^T + bias. 128x128 tile, BK=32, 8 warps
// (warp tile 64x32). 3-stage cp.async ring, ldmatrix fragments.
// ---------------------------------------------------------------------------
#define TPX 36
#define STG_WORDS ((128 + 128) * TPX)
#define GSMEM3 (3 * STG_WORDS * 4)

struct GJob { const float* A; const float* Bt; const float* bias;
              float* C; float* C2; int rnd; int pad; };
struct GJ3 { GJob j[3]; };

__global__ void __launch_bounds__(256, 2) gemm_tt_kernel(GJ3 gj, int M, int N, int K)
{
    extern __shared__ unsigned sm[];
    const GJob jb = gj.j[blockIdx.z];

    const int tid  = threadIdx.x;
    const int warp = tid >> 5;
    const int lane = tid & 31;
    const int m0 = blockIdx.y * 128;
    const int n0 = blockIdx.x * 128;
    const int wm0 = (warp >> 2) * 64;
    const int wn0 = (warp & 3) * 32;

    const int srow = tid >> 1;
    const int scol = (tid & 1) * 16;
    const float* Ag = jb.A  + (size_t)(m0 + srow) * K + scol;
    const float* Bg = jb.Bt + (size_t)(n0 + srow) * K + scol;
    const unsigned smb = sptr(sm);
    const unsigned sa = smb + (srow * TPX + scol) * 4;
    const unsigned sb = smb + (128 * TPX + srow * TPX + scol) * 4;

    const int lr  = (lane & 7) + ((lane >> 3) & 1) * 8;
    const int lc  = ((lane >> 4) & 1) * 4;
    const int brr = ((lane >> 4) & 1) * 8 + (lane & 7);
    const int bcc = ((lane >> 3) & 1) * 4;

    float acc[4][4][4];
    #pragma unroll
    for (int mt = 0; mt < 4; mt++)
        #pragma unroll
        for (int nt = 0; nt < 4; nt++)
            #pragma unroll
            for (int i = 0; i < 4; i++) acc[mt][nt][i] = 0.0f;

    const int T = K / 32;
    auto issue = [&](int st) {
        if (st < T) {
            const unsigned off = (unsigned)((st % 3) * STG_WORDS) * 4;
            const int ko = st * 32;
            #pragma unroll
            for (int i = 0; i < 4; i++) CP_ASYNC16(sa + off + i * 16, Ag + ko + i * 4);
            #pragma unroll
            for (int i = 0; i < 4; i++) CP_ASYNC16(sb + off + i * 16, Bg + ko + i * 4);
        }
        CP_COMMIT();
    };

    issue(0);
    issue(1);

    for (int t = 0; t < T; t++) {
        CP_WAIT1();
        __syncthreads();
        issue(t + 2);

        const unsigned so = (unsigned)((t % 3) * STG_WORDS);
        const unsigned ab = smb + (so + (wm0 + lr) * TPX + lc) * 4;
        const unsigned bb = smb + (so + 128 * TPX + (wn0 + brr) * TPX + bcc) * 4;
        #pragma unroll
        for (int ks = 0; ks < 4; ks++) {
            unsigned a[4][4];
            #pragma unroll
            for (int mt = 0; mt < 4; mt++)
                ldsm4(a[mt][0], a[mt][1], a[mt][2], a[mt][3],
                      ab + (unsigned)(mt * 16 * TPX + ks * 8) * 4);
            #pragma unroll
            for (int ntp = 0; ntp < 2; ntp++) {
                unsigned b0, b1, b2, b3;
                ldsm4(b0, b1, b2, b3, bb + (unsigned)(ntp * 16 * TPX + ks * 8) * 4);
                unsigned ba[2] = {b0, b1}, bx[2] = {b2, b3};
                #pragma unroll
                for (int mt = 0; mt < 4; mt++) {
                    mma8(acc[mt][2 * ntp],     a[mt], ba);
                    mma8(acc[mt][2 * ntp + 1], a[mt], bx);
                }
            }
        }
        __syncthreads();
    }

    #pragma unroll
    for (int mt = 0; mt < 4; mt++) {
        #pragma unroll
        for (int nt = 0; nt < 4; nt++) {
            int r0 = m0 + wm0 + mt * 16 + (lane >> 2);
            int c0 = n0 + wn0 + nt * 8 + 2 * (lane & 3);
            float b0 = jb.bias[c0], b1 = jb.bias[c0 + 1];
            float v0 = acc[mt][nt][0] + b0, v1 = acc[mt][nt][1] + b1;
            float v2 = acc[mt][nt][2] + b0, v3 = acc[mt][nt][3] + b1;
            size_t p0 = (size_t)r0 * N + c0;
            size_t p1 = (size_t)(r0 + 8) * N + c0;
            if (jb.C2) {
                uint2 u0 = {f2tf32(v0), f2tf32(v1)};
                uint2 u1 = {f2tf32(v2), f2tf32(v3)};
                *(uint2*)&jb.C2[p0] = u0;
                *(uint2*)&jb.C2[p1] = u1;
            }
            if (jb.rnd) {
                v0 = __uint_as_float(f2tf32(v0));
                v1 = __uint_as_float(f2tf32(v1));
                v2 = __uint_as_float(f2tf32(v2));
                v3 = __uint_as_float(f2tf32(v3));
            }
            float2 w0 = {v0, v1}, w1 = {v2, v3};
            *(float2*)&jb.C[p0] = w0;
            *(float2*)&jb.C[p1] = w1;
        }
    }
}

// ---------------------------------------------------------------------------
// Fused gate GEMM: gpre = [out_t|rec_t] @ WgT^T + bg (K=2048), then
// dst = out + sigmoid(gpre) * (rec - out). Same 128x128 3-stage pipeline.
// ---------------------------------------------------------------------------
__global__ void __launch_bounds__(256, 2) gemm_gate_kernel(
    const float* __restrict__ outT, const float* __restrict__ recT,
    const float* __restrict__ WgT_lo, const float* __restrict__ WgT_hi,
    const float* __restrict__ bias,
    const float* __restrict__ outF, const float* __restrict__ recF,
    float* __restrict__ dst, int N)
{
    extern __shared__ unsigned sm[];

    const int tid  = threadIdx.x;
    const int warp = tid >> 5;
    const int lane = tid & 31;
    const int m0 = blockIdx.y * 128;
    const int n0 = blockIdx.x * 128;
    const int wm0 = (warp >> 2) * 64;
    const int wn0 = (warp & 3) * 32;

    const int srow = tid >> 1;
    const int scol = (tid & 1) * 16;
    const size_t aoff = (size_t)(m0 + srow) * HID + scol;
    const size_t boff = (size_t)(n0 + srow) * HID + scol;
    const unsigned smb = sptr(sm);
    const unsigned sa = smb + (srow * TPX + scol) * 4;
    const unsigned sb = smb + (128 * TPX + srow * TPX + scol) * 4;

    const int lr  = (lane & 7) + ((lane >> 3) & 1) * 8;
    const int lc  = ((lane >> 4) & 1) * 4;
    const int brr = ((lane >> 4) & 1) * 8 + (lane & 7);
    const int bcc = ((lane >> 3) & 1) * 4;

    float acc[4][4][4];
    #pragma unroll
    for (int mt = 0; mt < 4; mt++)
        #pragma unroll
        for (int nt = 0; nt < 4; nt++)
            #pragma unroll
            for (int i = 0; i < 4; i++) acc[mt][nt][i] = 0.0f;

    const int T = (2 * HID) / 32;
    auto issue = [&](int st) {
        if (st < T) {
            const unsigned off = (unsigned)((st % 3) * STG_WORDS) * 4;
            const int kn = st * 32;
            const int ka = kn & (HID - 1);
            const float* As_ = (kn < HID) ? outT : recT;
            const float* Bs_ = (kn < HID) ? WgT_lo : WgT_hi;
            #pragma unroll
            for (int i = 0; i < 4; i++) CP_ASYNC16(sa + off + i * 16, As_ + aoff + ka + i * 4);
            #pragma unroll
            for (int i = 0; i < 4; i++) CP_ASYNC16(sb + off + i * 16, Bs_ + boff + ka + i * 4);
        }
        CP_COMMIT();
    };

    issue(0);
    issue(1);

    for (int t = 0; t < T; t++) {
        CP_WAIT1();
        __syncthreads();
        issue(t + 2);

        const unsigned so = (unsigned)((t % 3) * STG_WORDS);
        const unsigned ab = smb + (so + (wm0 + lr) * TPX + lc) * 4;
        const unsigned bb = smb + (so + 128 * TPX + (wn0 + brr) * TPX + bcc) * 4;
        #pragma unroll
        for (int ks = 0; ks < 4; ks++) {
            unsigned a[4][4];
            #pragma unroll
            for (int mt = 0; mt < 4; mt++)
                ldsm4(a[mt][0], a[mt][1], a[mt][2], a[mt][3],
                      ab + (unsigned)(mt * 16 * TPX + ks * 8) * 4);
            #pragma unroll
            for (int ntp = 0; ntp < 2; ntp++) {
                unsigned b0, b1, b2, b3;
                ldsm4(b0, b1, b2, b3, bb + (unsigned)(ntp * 16 * TPX + ks * 8) * 4);
                unsigned ba[2] = {b0, b1}, bx[2] = {b2, b3};
                #pragma unroll
                for (int mt = 0; mt < 4; mt++) {
                    mma8(acc[mt][2 * ntp],     a[mt], ba);
                    mma8(acc[mt][2 * ntp + 1], a[mt], bx);
                }
            }
        }
        __syncthreads();
    }

    #pragma unroll
    for (int mt = 0; mt < 4; mt++) {
        #pragma unroll
        for (int nt = 0; nt < 4; nt++) {
            int r0 = m0 + wm0 + mt * 16 + (lane >> 2);
            int c0 = n0 + wn0 + nt * 8 + 2 * (lane & 3);
            float b0 = bias[c0], b1 = bias[c0 + 1];
            float gp0 = acc[mt][nt][0] + b0, gp1 = acc[mt][nt][1] + b1;
            float gp2 = acc[mt][nt][2] + b0, gp3 = acc[mt][nt][3] + b1;
            size_t p0 = (size_t)r0 * N + c0;
            size_t p1 = (size_t)(r0 + 8) * N + c0;
            float2 o0 = *(const float2*)&outF[p0];
            float2 o1 = *(const float2*)&outF[p1];
            float2 rc0 = *(const float2*)&recF[p0];
            float2 rc1 = *(const float2*)&recF[p1];
            float gg0 = 1.0f / (1.0f + ex2f(-gp0 * LOG2E));
            float gg1 = 1.0f / (1.0f + ex2f(-gp1 * LOG2E));
            float gg2 = 1.0f / (1.0f + ex2f(-gp2 * LOG2E));
            float gg3 = 1.0f / (1.0f + ex2f(-gp3 * LOG2E));
            float2 w0 = {o0.x + gg0 * (rc0.x - o0.x), o0.y + gg1 * (rc0.y - o0.y)};
            float2 w1 = {o1.x + gg2 * (rc1.x - o1.x), o1.y + gg3 * (rc1.y - o1.y)};
            *(float2*)&dst[p0] = w0;
            *(float2*)&dst[p1] = w1;
        }
    }
}

// ---------------------------------------------------------------------------
// Flash attention (identical to round 7)
// ---------------------------------------------------------------------------
#define PW 68
#define ATTN_WORDS ((128 + 2 * 64 + 64) * PW)
#define ATTN_SMEM  (ATTN_WORDS * 4)

__global__ void __launch_bounds__(256, 2) attn_t_kernel(
    const float* __restrict__ Q, const float* __restrict__ K,
    const float* __restrict__ V, float* __restrict__ O)
{
    extern __shared__ unsigned sm[];
    unsigned* QP = sm;
    unsigned* KB = sm + 128 * PW;
    unsigned* VT = sm + (128 + 128) * PW;

    const size_t zoff = (size_t)blockIdx.z * SH;
    K += zoff; V += zoff; O += zoff;

    const int tid  = threadIdx.x;
    const int warp = tid >> 5;
    const int lane = tid & 31;
    const int hoff = blockIdx.y * HDIM;
    const int q0   = blockIdx.x * 128;

    const int lr  = (lane & 7) + ((lane >> 3) & 1) * 8;
    const int lc  = ((lane >> 4) & 1) * 4;
    const int brr = ((lane >> 4) & 1) * 8 + (lane & 7);
    const int bcc = ((lane >> 3) & 1) * 4;

    const int krow = tid >> 2;
    const int kcol = (tid & 3) * 16;

    {
        const int row = tid >> 1, half = tid & 1;
        const uint4* Qg = (const uint4*)(Q + (size_t)(q0 + row) * HID + hoff) + half * 8;
        uint4* Qs = (uint4*)&QP[row * PW + half * 32];
        #pragma unroll
        for (int j = 0; j < 8; j++) Qs[j] = Qg[j];
    }

    {
        unsigned d = sptr(&KB[krow * PW + kcol]);
        const float* g = K + (size_t)krow * HID + hoff + kcol;
        #pragma unroll
        for (int i = 0; i < 4; i++) CP_ASYNC16(d + i * 16, g + i * 4);
        CP_COMMIT();
    }
    __syncthreads();

    unsigned qa[8][4];
    {
        unsigned base = sptr(&QP[(warp * 16 + lr) * PW + lc]);
        #pragma unroll
        for (int g = 0; g < 8; g++)
            ldsm4(qa[g][0], qa[g][1], qa[g][2], qa[g][3], base + g * 32);
    }

    float o[8][4];
    #pragma unroll
    for (int nt = 0; nt < 8; nt++)
        #pragma unroll
        for (int i = 0; i < 4; i++) o[nt][i] = 0.0f;
    float mrow0 = -1e30f, mrow1 = -1e30f, lrow0 = 0.0f, lrow1 = 0.0f;

    const unsigned pbase  = sptr(&QP[(warp * 16 + lr) * PW + lc]);
    const unsigned vtbase = sptr(&VT[brr * PW]);
    const int vswz = (tid & 3) << 2;

    for (int tile = 0; tile < S_LEN / 64; tile++) {
        const int buf = tile & 1;

        uint4 vr[4];
        {
            const uint4* Vg = (const uint4*)(V + (size_t)(tile * 64 + krow) * HID + hoff + kcol);
            #pragma unroll
            for (int i = 0; i < 4; i++) vr[i] = Vg[i];
        }

        CP_WAIT0();
        __syncthreads();

        {
            const int col = krow ^ vswz;
            #pragma unroll
            for (int i = 0; i < 16; i++) {
                int d = (tid & 3) * 16 + i;
                VT[d * PW + col] = ((const unsigned*)vr)[i];
            }
        }

        if (tile + 1 < S_LEN / 64) {
            unsigned d = sptr(&KB[(buf ^ 1) * 64 * PW + krow * PW + kcol]);
            const float* g = K + (size_t)((tile + 1) * 64 + krow) * HID + hoff + kcol;
            #pragma unroll
            for (int i = 0; i < 4; i++) CP_ASYNC16(d + i * 16, g + i * 4);
        }
        CP_COMMIT();
        __syncthreads();

        float s[8][4];
        #pragma unroll
        for (int nt = 0; nt < 8; nt++)
            #pragma unroll
            for (int i = 0; i < 4; i++) s[nt][i] = 0.0f;

        {
            const unsigned kbase = sptr(&KB[buf * 64 * PW + brr * PW + bcc]);
            #pragma unroll
            for (int g = 0; g < 8; g++) {
                #pragma unroll
                for (int ntp = 0; ntp < 4; ntp++) {
                    unsigned b0, b1, b2, b3;
                    ldsm4(b0, b1, b2, b3, kbase + (unsigned)(ntp * 16 * PW + g * 8) * 4);
                    unsigned ba[2] = {b0, b1}, bb[2] = {b2, b3};
                    mma8(s[2 * ntp],     qa[g], ba);
                    mma8(s[2 * ntp + 1], qa[g], bb);
                }
            }
        }

        float mx0 = -1e30f, mx1 = -1e30f;
        #pragma unroll
        for (int nt = 0; nt < 8; nt++) {
            s[nt][0] *= SCL2; s[nt][1] *= SCL2;
            s[nt][2] *= SCL2; s[nt][3] *= SCL2;
            mx0 = fmaxf(mx0, fmaxf(s[nt][0], s[nt][1]));
            mx1 = fmaxf(mx1, fmaxf(s[nt][2], s[nt][3]));
        }
        mx0 = fmaxf(mx0, __shfl_xor_sync(0xffffffffu, mx0, 1));
        mx0 = fmaxf(mx0, __shfl_xor_sync(0xffffffffu, mx0, 2));
        mx1 = fmaxf(mx1, __shfl_xor_sync(0xffffffffu, mx1, 1));
        mx1 = fmaxf(mx1, __shfl_xor_sync(0xffffffffu, mx1, 2));

        float mn0 = fmaxf(mrow0, mx0);
        float mn1 = fmaxf(mrow1, mx1);
        float a0 = ex2f(mrow0 - mn0);
        float a1 = ex2f(mrow1 - mn1);

        {
            const int pr = lane >> 2;
            const int pc = 2 * (lane & 3);
            unsigned* P0 = &QP[(warp * 16 + pr) * PW + pc];
            unsigned* P1 = &QP[(warp * 16 + pr + 8) * PW + pc];
            float rs0 = 0.0f, rs1 = 0.0f;
            #pragma unroll
            for (int nt = 0; nt < 8; nt++) {
                float p0 = ex2f(s[nt][0] - mn0);
                float p1 = ex2f(s[nt][1] - mn0);
                float p2 = ex2f(s[nt][2] - mn1);
                float p3 = ex2f(s[nt][3] - mn1);
                rs0 += p0 + p1;
                rs1 += p2 + p3;
                uint2 w0 = {f2tf32(p0), f2tf32(p1)};
                uint2 w1 = {f2tf32(p2), f2tf32(p3)};
                *(uint2*)(P0 + nt * 8) = w0;
                *(uint2*)(P1 + nt * 8) = w1;
            }
            rs0 += __shfl_xor_sync(0xffffffffu, rs0, 1);
            rs0 += __shfl_xor_sync(0xffffffffu, rs0, 2);
            rs1 += __shfl_xor_sync(0xffffffffu, rs1, 1);
            rs1 += __shfl_xor_sync(0xffffffffu, rs1, 2);
            lrow0 = lrow0 * a0 + rs0;
            lrow1 = lrow1 * a1 + rs1;
            mrow0 = mn0; mrow1 = mn1;
        }
        #pragma unroll
        for (int nt = 0; nt < 8; nt++) {
            o[nt][0] *= a0; o[nt][1] *= a0;
            o[nt][2] *= a1; o[nt][3] *= a1;
        }
        __syncwarp();

        {
            #pragma unroll
            for (int g = 0; g < 8; g++) {
                unsigned pa[4];
                ldsm4(pa[0], pa[1], pa[2], pa[3], pbase + g * 32);
                #pragma unroll
                for (int ntp = 0; ntp < 4; ntp++) {
                    int cc = (g * 8 + bcc) ^ (ntp << 2);
                    unsigned b0, b1, b2, b3;
                    ldsm4(b0, b1, b2, b3, vtbase + (unsigned)(ntp * 16 * PW + cc) * 4);
                    unsigned ba[2] = {b0, b1}, bb[2] = {b2, b3};
                    mma8(o[2 * ntp],     pa, ba);
                    mma8(o[2 * ntp + 1], pa, bb);
                }
            }
        }
    }

    float i0 = 1.0f / lrow0;
    float i1 = 1.0f / lrow1;
    int r0 = q0 + warp * 16 + (lane >> 2);
    #pragma unroll
    for (int nt = 0; nt < 8; nt++) {
        int c = hoff + nt * 8 + 2 * (lane & 3);
        uint2 v0 = {f2tf32(o[nt][0] * i0), f2tf32(o[nt][1] * i0)};
        uint2 v1 = {f2tf32(o[nt][2] * i1), f2tf32(o[nt][3] * i1)};
        *(uint2*)&O[(size_t)r0 * HID + c] = v0;
        *(uint2*)&O[(size_t)(r0 + 8) * HID + c] = v1;
    }
}

// ---------------------------------------------------------------------------
// Combine: rec = 0.5*(a+b) in fp32 and tf32 copies
// ---------------------------------------------------------------------------
__global__ void combine_kernel(const float4* __restrict__ a,
                               const float4* __restrict__ b,
                               float4* __restrict__ oF,
                               float4* __restrict__ oT, int n4)
{
    int i = blockIdx.x * blockDim.x + threadIdx.x;
    if (i < n4) {
        float4 x = a[i], y = b[i], r;
        r.x = 0.5f * (x.x + y.x); r.y = 0.5f * (x.y + y.y);
        r.z = 0.5f * (x.z + y.z); r.w = 0.5f * (x.w + y.w);
        oF[i] = r;
        *(uint4*)&oT[i] = cvt4(r);
    }
}

// ---------------------------------------------------------------------------
// Launch — dual-stream fork/join captured into the graph.
// Stream B handles past-states prep + rk/rv GEMM (independent of the
// self-attention chain); joins before attn2.
// ---------------------------------------------------------------------------
extern "C" void kernel_launch(void* const* d_in, const int* in_sizes, int n_in,
                              void* d_out, int out_size)
{
    (void)in_sizes; (void)n_in; (void)out_size;

    const float* hs   = (const float*)d_in[0];
    const float* past = (const float*)d_in[1];
    const float* Wq = (const float*)d_in[2];  const float* bq = (const float*)d_in[3];
    const float* Wk = (const float*)d_in[4];  const float* bk = (const float*)d_in[5];
    const float* Wv = (const float*)d_in[6];  const float* bv = (const float*)d_in[7];
    const float* Wo = (const float*)d_in[8];  const float* bo = (const float*)d_in[9];
    const float* Wrq = (const float*)d_in[10]; const float* brq = (const float*)d_in[11];
    const float* Wrk = (const float*)d_in[12]; const float* brk = (const float*)d_in[13];
    const float* Wrv = (const float*)d_in[14]; const float* brv = (const float*)d_in[15];
    const float* Wg = (const float*)d_in[16];  const float* bg = (const float*)d_in[17];

    float *wt, *hs_t, *past_t, *q, *k, *v, *ctx_t, *out, *out_t, *rq, *rk, *rv,
          *rctx, *rec, *rec_t;
    cudaGetSymbolAddress((void**)&wt,     g_wt);
    cudaGetSymbolAddress((void**)&hs_t,   g_hs_t);
    cudaGetSymbolAddress((void**)&past_t, g_past_t);
    cudaGetSymbolAddress((void**)&q,      g_q);
    cudaGetSymbolAddress((void**)&k,      g_k);
    cudaGetSymbolAddress((void**)&v,      g_v);
    cudaGetSymbolAddress((void**)&ctx_t,  g_ctx_t);
    cudaGetSymbolAddress((void**)&out,    g_out);
    cudaGetSymbolAddress((void**)&out_t,  g_out_t);
    cudaGetSymbolAddress((void**)&rq,     g_rq);
    cudaGetSymbolAddress((void**)&rk,     g_rk);
    cudaGetSymbolAddress((void**)&rv,     g_rv);
    cudaGetSymbolAddress((void**)&rctx,   g_rctx);
    cudaGetSymbolAddress((void**)&rec,    g_rec);
    cudaGetSymbolAddress((void**)&rec_t,  g_rec_t);

    cudaFuncSetAttribute(attn_t_kernel,
                         cudaFuncAttributeMaxDynamicSharedMemorySize, ATTN_SMEM);
    cudaFuncSetAttribute(gemm_tt_kernel,
                         cudaFuncAttributeMaxDynamicSharedMemorySize, GSMEM3);
    cudaFuncSetAttribute(gemm_gate_kernel,
                         cudaFuncAttributeMaxDynamicSharedMemorySize, GSMEM3);

    // Side stream + events (created per call; intentionally not destroyed —
    // kernel_launch runs only for correctness + capture, never in the timed
    // replay loop, so the handful of leaked handles is harmless).
    cudaStream_t sB;
    cudaStreamCreateWithFlags(&sB, cudaStreamNonBlocking);
    cudaEvent_t evFork, evJoin;
    cudaEventCreateWithFlags(&evFork, cudaEventDisableTiming);
    cudaEventCreateWithFlags(&evJoin, cudaEventDisableTiming);

    #define WT(i) (wt + (size_t)(i) * HID * HID)

    // --- prep (main stream): weight transpose + hs rounding ---
    {
        P9 ws = {{Wq, Wk, Wv, Wo, Wrq, Wrk, Wrv, Wg, Wg + (size_t)HID * HID}};
        prep_wt_kernel<<<dim3(32, 32, 9), 256>>>(ws, wt);
    }
    cudaEventRecord(evFork, cudaStreamPerThread);
    cudaStreamWaitEvent(sB, evFork, 0);

    prep_rnd_kernel<<<SH / 4 / 256, 256>>>((const float4*)hs, (float4*)hs_t, SH / 4);

    // --- stream B: past prep + rk/rv GEMM (independent of attn1 chain) ---
    prep_rnd_kernel<<<2 * SH / 4 / 256, 256, 0, sB>>>(
        (const float4*)past, (float4*)past_t, 2 * SH / 4);
    {
        GJ3 gj = {{{past_t, WT(5), brk, rk, 0, 1, 0},
                   {past_t, WT(6), brv, rv, 0, 1, 0}, {}}};
        gemm_tt_kernel<<<dim3(8, 32, 2), 256, GSMEM3, sB>>>(gj, 2 * S_LEN, HID, HID);
    }
    cudaEventRecord(evJoin, sB);

    // --- main stream: self attention chain ---
    {
        GJ3 gj = {{{hs_t, WT(0), bq, q, 0, 1, 0},
                   {hs_t, WT(1), bk, k, 0, 1, 0},
                   {hs_t, WT(2), bv, v, 0, 1, 0}}};
        gemm_tt_kernel<<<dim3(8, 16, 3), 256, GSMEM3>>>(gj, S_LEN, HID, HID);
    }
    attn_t_kernel<<<dim3(16, 16, 1), 256, ATTN_SMEM>>>(q, k, v, ctx_t);
    {
        GJ3 gj = {{{ctx_t, WT(3), bo, out, out_t, 0, 0}, {}, {}}};
        gemm_tt_kernel<<<dim3(8, 16, 1), 256, GSMEM3>>>(gj, S_LEN, HID, HID);
    }
    {
        GJ3 gj = {{{out_t, WT(4), brq, rq, 0, 1, 0}, {}, {}}};
        gemm_tt_kernel<<<dim3(8, 16, 1), 256, GSMEM3>>>(gj, S_LEN, HID, HID);
    }

    // --- join stream B, then recursive attention ---
    cudaStreamWaitEvent(cudaStreamPerThread, evJoin, 0);
    attn_t_kernel<<<dim3(16, 16, 2), 256, ATTN_SMEM>>>(rq, rk, rv, rctx);
    combine_kernel<<<SH / 4 / 256, 256>>>((const float4*)rctx,
                                          (const float4*)(rctx + SH),
                                          (float4*)rec, (float4*)rec_t, SH / 4);

    // --- fused gate + blend -> d_out ---
    gemm_gate_kernel<<<dim3(8, 16), 256, GSMEM3>>>(out_t, rec_t, WT(7), WT(8), bg,
                                                   out, rec, (float*)d_out, HID);
}

// round 10
// speedup vs baseline: 1.1051x; 1.0109x over previous
#include <cuda_runtime.h>
#include <math.h>
#include <stdint.h>

// Problem constants
#define S_LEN 2048
#define HID   1024
#define NHEAD 16
#define HDIM  64
#define SH    (S_LEN * HID)
#define SCL2  0.1803368801111204f   // (1/sqrt(64)) * log2(e)
#define LOG2E 1.4426950408889634f

// ---------------------------------------------------------------------------
// Scratch
// ---------------------------------------------------------------------------
__device__ float g_wt[9 * HID * HID];   // 9 transposed tf32 weights [n][k]
__device__ float g_hs_t[SH];
__device__ float g_past_t[2 * SH];
__device__ float g_q[SH];
__device__ float g_k[SH];
__device__ float g_vt[SH];      // [NHEAD][HDIM][S_LEN]
__device__ float g_ctx_t[SH];
__device__ float g_out[SH];
__device__ float g_out_t[SH];
__device__ float g_rq[SH];
__device__ float g_rk[2 * SH];
__device__ float g_rvt[2 * SH]; // [NHEAD][HDIM][2*S_LEN]
__device__ float g_rctx[2 * SH];
__device__ float g_rec[SH];
__device__ float g_rec_t[SH];

// ---------------------------------------------------------------------------
// helpers
// ---------------------------------------------------------------------------
__device__ __forceinline__ unsigned f2tf32(float x) {
    unsigned r;
    asm("cvt.rna.tf32.f32 %0, %1;" : "=r"(r) : "f"(x));
    return r;
}
__device__ __forceinline__ uint4 cvt4(float4 v) {
    uint4 r;
    r.x = f2tf32(v.x); r.y = f2tf32(v.y);
    r.z = f2tf32(v.z); r.w = f2tf32(v.w);
    return r;
}
__device__ __forceinline__ void mma8(float* c, const unsigned* a, const unsigned* b) {
    asm volatile(
        "mma.sync.aligned.m16n8k8.row.col.f32.tf32.tf32.f32 "
        "{%0,%1,%2,%3}, {%4,%5,%6,%7}, {%8,%9}, {%0,%1,%2,%3};\n"
        : "+f"(c[0]), "+f"(c[1]), "+f"(c[2]), "+f"(c[3])
        : "r"(a[0]), "r"(a[1]), "r"(a[2]), "r"(a[3]), "r"(b[0]), "r"(b[1]));
}
__device__ __forceinline__ void ldsm4(unsigned &r0, unsigned &r1,
                                      unsigned &r2, unsigned &r3, unsigned a) {
    asm volatile("ldmatrix.sync.aligned.m8n8.x4.shared.b16 {%0,%1,%2,%3}, [%4];"
        : "=r"(r0), "=r"(r1), "=r"(r2), "=r"(r3) : "r"(a));
}
__device__ __forceinline__ unsigned sptr(const void* p) {
    return (unsigned)__cvta_generic_to_shared(p);
}
__device__ __forceinline__ float ex2f(float x) {
    float y; asm("ex2.approx.ftz.f32 %0, %1;" : "=f"(y) : "f"(x)); return y;
}
#define CP_ASYNC16(dst, src) \
    asm volatile("cp.async.cg.shared.global [%0], [%1], 16;" :: "r"(dst), "l"(src) : "memory")
#define CP_COMMIT() asm volatile("cp.async.commit_group;" ::: "memory")
#define CP_WAIT0()  asm volatile("cp.async.wait_group 0;" ::: "memory")
#define CP_WAIT1()  asm volatile("cp.async.wait_group 1;" ::: "memory")

// ---------------------------------------------------------------------------
// Prep kernels
// ---------------------------------------------------------------------------
struct P9 { const float* p[9]; };

__global__ void __launch_bounds__(256) prep_wt_kernel(P9 ws, float* __restrict__ dst)
{
    __shared__ float t[32][33];
    const float* __restrict__ src = ws.p[blockIdx.z];
    float* __restrict__ d = dst + (size_t)blockIdx.z * HID * HID;
    const int r0 = blockIdx.y * 32, c0 = blockIdx.x * 32;
    const int lr = threadIdx.x >> 3, lc = (threadIdx.x & 7) * 4;

    float4 v = *(const float4*)&src[(size_t)(r0 + lr) * HID + c0 + lc];
    t[lr][lc] = v.x; t[lr][lc + 1] = v.y; t[lr][lc + 2] = v.z; t[lr][lc + 3] = v.w;
    __syncthreads();

    uint4 w;
    w.x = f2tf32(t[lc + 0][lr]);
    w.y = f2tf32(t[lc + 1][lr]);
    w.z = f2tf32(t[lc + 2][lr]);
    w.w = f2tf32(t[lc + 3][lr]);
    *(uint4*)&d[(size_t)(c0 + lr) * HID + r0 + lc] = w;
}

__global__ void prep_rnd_kernel(const float4* __restrict__ s,
                                float4* __restrict__ d, int n4)
{
    int i = blockIdx.x * blockDim.x + threadIdx.x;
    if (i < n4) *(uint4*)&d[i] = cvt4(s[i]);
}

// ---------------------------------------------------------------------------
// GEMM: C[M,N] = A[M,K] @ Bt[N,K]^T + bias. 128x128 tile, BK=32, 8 warps
// (warp tile 64x32). 3-stage cp.async ring, ldmatrix fragments.
// C optional; C2 = extra tf32 copy; CT = transposed copy ct[c*M + r]
// (per-head [h][d][row] layout since heads are contiguous 64-col groups).
// ---------------------------------------------------------------------------
#define TPX 36
#define STG_WORDS ((128 + 128) * TPX)
#define GSMEM3 (3 * STG_WORDS * 4)

struct GJob { const float* A; const float* Bt; const float* bias;
              float* C; float* C2; float* CT; int rnd; int pad; };
struct GJ3 { GJob j[3]; };

__global__ void __launch_bounds__(256, 2) gemm_tt_kernel(GJ3 gj, int M, int N, int K)
{
    extern __shared__ unsigned sm[];
    const GJob jb = gj.j[blockIdx.z];

    const int tid  = threadIdx.x;
    const int warp = tid >> 5;
    const int lane = tid & 31;
    const int m0 = blockIdx.y * 128;
    const int n0 = blockIdx.x * 128;
    const int wm0 = (warp >> 2) * 64;
    const int wn0 = (warp & 3) * 32;

    const int srow = tid >> 1;
    const int scol = (tid & 1) * 16;
    const float* Ag = jb.A  + (size_t)(m0 + srow) * K + scol;
    const float* Bg = jb.Bt + (size_t)(n0 + srow) * K + scol;
    const unsigned smb = sptr(sm);
    const unsigned sa = smb + (srow * TPX + scol) * 4;
    const unsigned sb = smb + (128 * TPX + srow * TPX + scol) * 4;

    const int lr  = (lane & 7) + ((lane >> 3) & 1) * 8;
    const int lc  = ((lane >> 4) & 1) * 4;
    const int brr = ((lane >> 4) & 1) * 8 + (lane & 7);
    const int bcc = ((lane >> 3) & 1) * 4;

    float acc[4][4][4];
    #pragma unroll
    for (int mt = 0; mt < 4; mt++)
        #pragma unroll
        for (int nt = 0; nt < 4; nt++)
            #pragma unroll
            for (int i = 0; i < 4; i++) acc[mt][nt][i] = 0.0f;

    const int T = K / 32;
    auto issue = [&](int st) {
        if (st < T) {
            const unsigned off = (unsigned)((st % 3) * STG_WORDS) * 4;
            const int ko = st * 32;
            #pragma unroll
            for (int i = 0; i < 4; i++) CP_ASYNC16(sa + off + i * 16, Ag + ko + i * 4);
            #pragma unroll
            for (int i = 0; i < 4; i++) CP_ASYNC16(sb + off + i * 16, Bg + ko + i * 4);
        }
        CP_COMMIT();
    };

    issue(0);
    issue(1);

    for (int t = 0; t < T; t++) {
        CP_WAIT1();
        __syncthreads();
        issue(t + 2);

        const unsigned so = (unsigned)((t % 3) * STG_WORDS);
        const unsigned ab = smb + (so + (wm0 + lr) * TPX + lc) * 4;
        const unsigned bb = smb + (so + 128 * TPX + (wn0 + brr) * TPX + bcc) * 4;
        #pragma unroll
        for (int ks = 0; ks < 4; ks++) {
            unsigned a[4][4];
            #pragma unroll
            for (int mt = 0; mt < 4; mt++)
                ldsm4(a[mt][0], a[mt][1], a[mt][2], a[mt][3],
                      ab + (unsigned)(mt * 16 * TPX + ks * 8) * 4);
            #pragma unroll
            for (int ntp = 0; ntp < 2; ntp++) {
                unsigned b0, b1, b2, b3;
                ldsm4(b0, b1, b2, b3, bb + (unsigned)(ntp * 16 * TPX + ks * 8) * 4);
                unsigned ba[2] = {b0, b1}, bx[2] = {b2, b3};
                #pragma unroll
                for (int mt = 0; mt < 4; mt++) {
                    mma8(acc[mt][2 * ntp],     a[mt], ba);
                    mma8(acc[mt][2 * ntp + 1], a[mt], bx);
                }
            }
        }
        __syncthreads();
    }

    #pragma unroll
    for (int mt = 0; mt < 4; mt++) {
        #pragma unroll
        for (int nt = 0; nt < 4; nt++) {
            int r0 = m0 + wm0 + mt * 16 + (lane >> 2);
            int c0 = n0 + wn0 + nt * 8 + 2 * (lane & 3);
            float b0 = jb.bias[c0], b1 = jb.bias[c0 + 1];
            float v0 = acc[mt][nt][0] + b0, v1 = acc[mt][nt][1] + b1;
            float v2 = acc[mt][nt][2] + b0, v3 = acc[mt][nt][3] + b1;
            size_t p0 = (size_t)r0 * N + c0;
            size_t p1 = (size_t)(r0 + 8) * N + c0;
            if (jb.C2) {
                uint2 u0 = {f2tf32(v0), f2tf32(v1)};
                uint2 u1 = {f2tf32(v2), f2tf32(v3)};
                *(uint2*)&jb.C2[p0] = u0;
                *(uint2*)&jb.C2[p1] = u1;
            }
            if (jb.rnd) {
                v0 = __uint_as_float(f2tf32(v0));
                v1 = __uint_as_float(f2tf32(v1));
                v2 = __uint_as_float(f2tf32(v2));
                v3 = __uint_as_float(f2tf32(v3));
            }
            if (jb.CT) {
                jb.CT[(size_t)c0 * M + r0]           = v0;
                jb.CT[(size_t)(c0 + 1) * M + r0]     = v1;
                jb.CT[(size_t)c0 * M + r0 + 8]       = v2;
                jb.CT[(size_t)(c0 + 1) * M + r0 + 8] = v3;
            }
            if (jb.C) {
                float2 w0 = {v0, v1}, w1 = {v2, v3};
                *(float2*)&jb.C[p0] = w0;
                *(float2*)&jb.C[p1] = w1;
            }
        }
    }
}

// ---------------------------------------------------------------------------
// Fused gate GEMM: gpre = [out_t|rec_t] @ WgT^T + bg (K=2048), then
// dst = out + sigmoid(gpre) * (rec - out). Same 128x128 3-stage pipeline.
// ---------------------------------------------------------------------------
__global__ void __launch_bounds__(256, 2) gemm_gate_kernel(
    const float* __restrict__ outT, const float* __restrict__ recT,
    const float* __restrict__ WgT_lo, const float* __restrict__ WgT_hi,
    const float* __restrict__ bias,
    const float* __restrict__ outF, const float* __restrict__ recF,
    float* __restrict__ dst, int N)
{
    extern __shared__ unsigned sm[];

    const int tid  = threadIdx.x;
    const int warp = tid >> 5;
    const int lane = tid & 31;
    const int m0 = blockIdx.y * 128;
    const int n0 = blockIdx.x * 128;
    const int wm0 = (warp >> 2) * 64;
    const int wn0 = (warp & 3) * 32;

    const int srow = tid >> 1;
    const int scol = (tid & 1) * 16;
    const size_t aoff = (size_t)(m0 + srow) * HID + scol;
    const size_t boff = (size_t)(n0 + srow) * HID + scol;
    const unsigned smb = sptr(sm);
    const unsigned sa = smb + (srow * TPX + scol) * 4;
    const unsigned sb = smb + (128 * TPX + srow * TPX + scol) * 4;

    const int lr  = (lane & 7) + ((lane >> 3) & 1) * 8;
    const int lc  = ((lane >> 4) & 1) * 4;
    const int brr = ((lane >> 4) & 1) * 8 + (lane & 7);
    const int bcc = ((lane >> 3) & 1) * 4;

    float acc[4][4][4];
    #pragma unroll
    for (int mt = 0; mt < 4; mt++)
        #pragma unroll
        for (int nt = 0; nt < 4; nt++)
            #pragma unroll
            for (int i = 0; i < 4; i++) acc[mt][nt][i] = 0.0f;

    const int T = (2 * HID) / 32;
    auto issue = [&](int st) {
        if (st < T) {
            const unsigned off = (unsigned)((st % 3) * STG_WORDS) * 4;
            const int kn = st * 32;
            const int ka = kn & (HID - 1);
            const float* As_ = (kn < HID) ? outT : recT;
            const float* Bs_ = (kn < HID) ? WgT_lo : WgT_hi;
            #pragma unroll
            for (int i = 0; i < 4; i++) CP_ASYNC16(sa + off + i * 16, As_ + aoff + ka + i * 4);
            #pragma unroll
            for (int i = 0; i < 4; i++) CP_ASYNC16(sb + off + i * 16, Bs_ + boff + ka + i * 4);
        }
        CP_COMMIT();
    };

    issue(0);
    issue(1);

    for (int t = 0; t < T; t++) {
        CP_WAIT1();
        __syncthreads();
        issue(t + 2);

        const unsigned so = (unsigned)((t % 3) * STG_WORDS);
        const unsigned ab = smb + (so + (wm0 + lr) * TPX + lc) * 4;
        const unsigned bb = smb + (so + 128 * TPX + (wn0 + brr) * TPX + bcc) * 4;
        #pragma unroll
        for (int ks = 0; ks < 4; ks++) {
            unsigned a[4][4];
            #pragma unroll
            for (int mt = 0; mt < 4; mt++)
                ldsm4(a[mt][0], a[mt][1], a[mt][2], a[mt][3],
                      ab + (unsigned)(mt * 16 * TPX + ks * 8) * 4);
            #pragma unroll
            for (int ntp = 0; ntp < 2; ntp++) {
                unsigned b0, b1, b2, b3;
                ldsm4(b0, b1, b2, b3, bb + (unsigned)(ntp * 16 * TPX + ks * 8) * 4);
                unsigned ba[2] = {b0, b1}, bx[2] = {b2, b3};
                #pragma unroll
                for (int mt = 0; mt < 4; mt++) {
                    mma8(acc[mt][2 * ntp],     a[mt], ba);
                    mma8(acc[mt][2 * ntp + 1], a[mt], bx);
                }
            }
        }
        __syncthreads();
    }

    #pragma unroll
    for (int mt = 0; mt < 4; mt++) {
        #pragma unroll
        for (int nt = 0; nt < 4; nt++) {
            int r0 = m0 + wm0 + mt * 16 + (lane >> 2);
            int c0 = n0 + wn0 + nt * 8 + 2 * (lane & 3);
            float b0 = bias[c0], b1 = bias[c0 + 1];
            float gp0 = acc[mt][nt][0] + b0, gp1 = acc[mt][nt][1] + b1;
            float gp2 = acc[mt][nt][2] + b0, gp3 = acc[mt][nt][3] + b1;
            size_t p0 = (size_t)r0 * N + c0;
            size_t p1 = (size_t)(r0 + 8) * N + c0;
            float2 o0 = *(const float2*)&outF[p0];
            float2 o1 = *(const float2*)&outF[p1];
            float2 rc0 = *(const float2*)&recF[p0];
            float2 rc1 = *(const float2*)&recF[p1];
            float gg0 = 1.0f / (1.0f + ex2f(-gp0 * LOG2E));
            float gg1 = 1.0f / (1.0f + ex2f(-gp1 * LOG2E));
            float gg2 = 1.0f / (1.0f + ex2f(-gp2 * LOG2E));
            float gg3 = 1.0f / (1.0f + ex2f(-gp3 * LOG2E));
            float2 w0 = {o0.x + gg0 * (rc0.x - o0.x), o0.y + gg1 * (rc0.y - o0.y)};
            float2 w1 = {o1.x + gg2 * (rc1.x - o1.x), o1.y + gg3 * (rc1.y - o1.y)};
            *(float2*)&dst[p0] = w0;
            *(float2*)&dst[p1] = w1;
        }
    }
}

// ---------------------------------------------------------------------------
// Flash attention v4: V pre-transposed in global ([h][d][keys]). Both K and
// Vt tiles cp.async double-buffered in one commit group; one sync per tile.
// PV B-fragments via plain ldmatrix (same pattern as QK path).
// ---------------------------------------------------------------------------
#define PW 68
#define ATTN_WORDS ((128 + 128 + 128) * PW)   // QP + 2xK + 2xVt
#define ATTN_SMEM  (ATTN_WORDS * 4)

__global__ void __launch_bounds__(256, 2) attn_t_kernel(
    const float* __restrict__ Q, const float* __restrict__ K,
    const float* __restrict__ Vt, float* __restrict__ O, int Mv)
{
    extern __shared__ unsigned sm[];
    unsigned* QP = sm;                 // [128][PW] Q then P
    unsigned* KB = sm + 128 * PW;      // 2 x [64][PW]
    unsigned* VB = sm + 256 * PW;      // 2 x [64][PW], d-major (pre-transposed)

    const size_t zoff = (size_t)blockIdx.z * SH;
    K += zoff; O += zoff;

    const int tid  = threadIdx.x;
    const int warp = tid >> 5;
    const int lane = tid & 31;
    const int hoff = blockIdx.y * HDIM;
    const int q0   = blockIdx.x * 128;

    // Vt base for this (head, z): [h][d][keys], z selects key block
    const float* Vtb = Vt + (size_t)hoff * Mv + (size_t)blockIdx.z * S_LEN;

    const int lr  = (lane & 7) + ((lane >> 3) & 1) * 8;
    const int lc  = ((lane >> 4) & 1) * 4;
    const int brr = ((lane >> 4) & 1) * 8 + (lane & 7);
    const int bcc = ((lane >> 3) & 1) * 4;

    const int krow = tid >> 2;          // 0..63
    const int kcol = (tid & 3) * 16;    // 0..48

    // Stage Q (natural)
    {
        const int row = tid >> 1, half = tid & 1;
        const uint4* Qg = (const uint4*)(Q + (size_t)(q0 + row) * HID + hoff) + half * 8;
        uint4* Qs = (uint4*)&QP[row * PW + half * 32];
        #pragma unroll
        for (int j = 0; j < 8; j++) Qs[j] = Qg[j];
    }

    auto issueKV = [&](int s) {
        const unsigned bo = (unsigned)((s & 1) * 64 * PW);
        unsigned kd = sptr(&KB[bo + krow * PW + kcol]);
        const float* kg = K + (size_t)(s * 64 + krow) * HID + hoff + kcol;
        #pragma unroll
        for (int i = 0; i < 4; i++) CP_ASYNC16(kd + i * 16, kg + i * 4);
        unsigned vd = sptr(&VB[bo + krow * PW + kcol]);
        const float* vg = Vtb + (size_t)krow * Mv + s * 64 + kcol;
        #pragma unroll
        for (int i = 0; i < 4; i++) CP_ASYNC16(vd + i * 16, vg + i * 4);
    };

    issueKV(0);
    CP_COMMIT();
    __syncthreads();

    // Resident Q fragments
    unsigned qa[8][4];
    {
        unsigned base = sptr(&QP[(warp * 16 + lr) * PW + lc]);
        #pragma unroll
        for (int g = 0; g < 8; g++)
            ldsm4(qa[g][0], qa[g][1], qa[g][2], qa[g][3], base + g * 32);
    }

    float o[8][4];
    #pragma unroll
    for (int nt = 0; nt < 8; nt++)
        #pragma unroll
        for (int i = 0; i < 4; i++) o[nt][i] = 0.0f;
    float mrow0 = -1e30f, mrow1 = -1e30f, lrow0 = 0.0f, lrow1 = 0.0f;

    const unsigned pbase  = sptr(&QP[(warp * 16 + lr) * PW + lc]);
    const unsigned kbase0 = sptr(KB) + (unsigned)(brr * PW + bcc) * 4;
    const unsigned vbase0 = sptr(VB) + (unsigned)(brr * PW + bcc) * 4;

    const int T = S_LEN / 64;
    for (int tile = 0; tile < T; tile++) {
        CP_WAIT0();
        __syncthreads();
        if (tile + 1 < T) issueKV(tile + 1);
        CP_COMMIT();

        const unsigned so = (unsigned)((tile & 1) * 64 * PW) * 4;

        // --- S = Q K^T ---
        float s[8][4];
        #pragma unroll
        for (int nt = 0; nt < 8; nt++)
            #pragma unroll
            for (int i = 0; i < 4; i++) s[nt][i] = 0.0f;

        {
            const unsigned kbase = kbase0 + so;
            #pragma unroll
            for (int g = 0; g < 8; g++) {
                #pragma unroll
                for (int ntp = 0; ntp < 4; ntp++) {
                    unsigned b0, b1, b2, b3;
                    ldsm4(b0, b1, b2, b3, kbase + (unsigned)(ntp * 16 * PW + g * 8) * 4);
                    unsigned ba[2] = {b0, b1}, bb[2] = {b2, b3};
                    mma8(s[2 * ntp],     qa[g], ba);
                    mma8(s[2 * ntp + 1], qa[g], bb);
                }
            }
        }

        // --- Online softmax (log2 domain) ---
        float mx0 = -1e30f, mx1 = -1e30f;
        #pragma unroll
        for (int nt = 0; nt < 8; nt++) {
            s[nt][0] *= SCL2; s[nt][1] *= SCL2;
            s[nt][2] *= SCL2; s[nt][3] *= SCL2;
            mx0 = fmaxf(mx0, fmaxf(s[nt][0], s[nt][1]));
            mx1 = fmaxf(mx1, fmaxf(s[nt][2], s[nt][3]));
        }
        mx0 = fmaxf(mx0, __shfl_xor_sync(0xffffffffu, mx0, 1));
        mx0 = fmaxf(mx0, __shfl_xor_sync(0xffffffffu, mx0, 2));
        mx1 = fmaxf(mx1, __shfl_xor_sync(0xffffffffu, mx1, 1));
        mx1 = fmaxf(mx1, __shfl_xor_sync(0xffffffffu, mx1, 2));

        float mn0 = fmaxf(mrow0, mx0);
        float mn1 = fmaxf(mrow1, mx1);
        float a0 = ex2f(mrow0 - mn0);
        float a1 = ex2f(mrow1 - mn1);

        {
            const int pr = lane >> 2;
            const int pc = 2 * (lane & 3);
            unsigned* P0 = &QP[(warp * 16 + pr) * PW + pc];
            unsigned* P1 = &QP[(warp * 16 + pr + 8) * PW + pc];
            float rs0 = 0.0f, rs1 = 0.0f;
            #pragma unroll
            for (int nt = 0; nt < 8; nt++) {
                float p0 = ex2f(s[nt][0] - mn0);
                float p1 = ex2f(s[nt][1] - mn0);
                float p2 = ex2f(s[nt][2] - mn1);
                float p3 = ex2f(s[nt][3] - mn1);
                rs0 += p0 + p1;
                rs1 += p2 + p3;
                uint2 w0 = {f2tf32(p0), f2tf32(p1)};
                uint2 w1 = {f2tf32(p2), f2tf32(p3)};
                *(uint2*)(P0 + nt * 8) = w0;
                *(uint2*)(P1 + nt * 8) = w1;
            }
            rs0 += __shfl_xor_sync(0xffffffffu, rs0, 1);
            rs0 += __shfl_xor_sync(0xffffffffu, rs0, 2);
            rs1 += __shfl_xor_sync(0xffffffffu, rs1, 1);
            rs1 += __shfl_xor_sync(0xffffffffu, rs1, 2);
            lrow0 = lrow0 * a0 + rs0;
            lrow1 = lrow1 * a1 + rs1;
            mrow0 = mn0; mrow1 = mn1;
        }
        #pragma unroll
        for (int nt = 0; nt < 8; nt++) {
            o[nt][0] *= a0; o[nt][1] *= a0;
            o[nt][2] *= a1; o[nt][3] *= a1;
        }
        __syncwarp();

        // --- O += P @ V (Vt d-major, plain ldmatrix) ---
        {
            const unsigned vbase = vbase0 + so;
            #pragma unroll
            for (int g = 0; g < 8; g++) {
                unsigned pa[4];
                ldsm4(pa[0], pa[1], pa[2], pa[3], pbase + g * 32);
                #pragma unroll
                for (int ntp = 0; ntp < 4; ntp++) {
                    unsigned b0, b1, b2, b3;
                    ldsm4(b0, b1, b2, b3, vbase + (unsigned)(ntp * 16 * PW + g * 8) * 4);
                    unsigned ba[2] = {b0, b1}, bb[2] = {b2, b3};
                    mma8(o[2 * ntp],     pa, ba);
                    mma8(o[2 * ntp + 1], pa, bb);
                }
            }
        }
    }

    // Write O (tf32-rounded; consumed as GEMM A operand)
    float i0 = 1.0f / lrow0;
    float i1 = 1.0f / lrow1;
    int r0 = q0 + warp * 16 + (lane >> 2);
    #pragma unroll
    for (int nt = 0; nt < 8; nt++) {
        int c = hoff + nt * 8 + 2 * (lane & 3);
        uint2 v0 = {f2tf32(o[nt][0] * i0), f2tf32(o[nt][1] * i0)};
        uint2 v1 = {f2tf32(o[nt][2] * i1), f2tf32(o[nt][3] * i1)};
        *(uint2*)&O[(size_t)r0 * HID + c] = v0;
        *(uint2*)&O[(size_t)(r0 + 8) * HID + c] = v1;
    }
}

// ---------------------------------------------------------------------------
// Combine: rec = 0.5*(a+b) in fp32 and tf32 copies
// ---------------------------------------------------------------------------
__global__ void combine_kernel(const float4* __restrict__ a,
                               const float4* __restrict__ b,
                               float4* __restrict__ oF,
                               float4* __restrict__ oT, int n4)
{
    int i = blockIdx.x * blockDim.x + threadIdx.x;
    if (i < n4) {
        float4 x = a[i], y = b[i], r;
        r.x = 0.5f * (x.x + y.x); r.y = 0.5f * (x.y + y.y);
        r.z = 0.5f * (x.z + y.z); r.w = 0.5f * (x.w + y.w);
        oF[i] = r;
        *(uint4*)&oT[i] = cvt4(r);
    }
}

// ---------------------------------------------------------------------------
// Launch — dual-stream fork/join captured into the graph.
// ---------------------------------------------------------------------------
extern "C" void kernel_launch(void* const* d_in, const int* in_sizes, int n_in,
                              void* d_out, int out_size)
{
    (void)in_sizes; (void)n_in; (void)out_size;

    const float* hs   = (const float*)d_in[0];
    const float* past = (const float*)d_in[1];
    const float* Wq = (const float*)d_in[2];  const float* bq = (const float*)d_in[3];
    const float* Wk = (const float*)d_in[4];  const float* bk = (const float*)d_in[5];
    const float* Wv = (const float*)d_in[6];  const float* bv = (const float*)d_in[7];
    const float* Wo = (const float*)d_in[8];  const float* bo = (const float*)d_in[9];
    const float* Wrq = (const float*)d_in[10]; const float* brq = (const float*)d_in[11];
    const float* Wrk = (const float*)d_in[12]; const float* brk = (const float*)d_in[13];
    const float* Wrv = (const float*)d_in[14]; const float* brv = (const float*)d_in[15];
    const float* Wg = (const float*)d_in[16];  const float* bg = (const float*)d_in[17];

    float *wt, *hs_t, *past_t, *q, *k, *vt, *ctx_t, *out, *out_t, *rq, *rk, *rvt,
          *rctx, *rec, *rec_t;
    cudaGetSymbolAddress((void**)&wt,     g_wt);
    cudaGetSymbolAddress((void**)&hs_t,   g_hs_t);
    cudaGetSymbolAddress((void**)&past_t, g_past_t);
    cudaGetSymbolAddress((void**)&q,      g_q);
    cudaGetSymbolAddress((void**)&k,      g_k);
    cudaGetSymbolAddress((void**)&vt,     g_vt);
    cudaGetSymbolAddress((void**)&ctx_t,  g_ctx_t);
    cudaGetSymbolAddress((void**)&out,    g_out);
    cudaGetSymbolAddress((void**)&out_t,  g_out_t);
    cudaGetSymbolAddress((void**)&rq,     g_rq);
    cudaGetSymbolAddress((void**)&rk,     g_rk);
    cudaGetSymbolAddress((void**)&rvt,    g_rvt);
    cudaGetSymbolAddress((void**)&rctx,   g_rctx);
    cudaGetSymbolAddress((void**)&rec,    g_rec);
    cudaGetSymbolAddress((void**)&rec_t,  g_rec_t);

    cudaFuncSetAttribute(attn_t_kernel,
                         cudaFuncAttributeMaxDynamicSharedMemorySize, ATTN_SMEM);
    cudaFuncSetAttribute(gemm_tt_kernel,
                         cudaFuncAttributeMaxDynamicSharedMemorySize, GSMEM3);
    cudaFuncSetAttribute(gemm_gate_kernel,
                         cudaFuncAttributeMaxDynamicSharedMemorySize, GSMEM3);

    cudaStream_t sB;
    cudaStreamCreateWithFlags(&sB, cudaStreamNonBlocking);
    cudaEvent_t evFork, evJoin;
    cudaEventCreateWithFlags(&evFork, cudaEventDisableTiming);
    cudaEventCreateWithFlags(&evJoin, cudaEventDisableTiming);

    #define WT(i) (wt + (size_t)(i) * HID * HID)

    // --- prep (main stream): weight transpose + hs rounding ---
    {
        P9 ws = {{Wq, Wk, Wv, Wo, Wrq, Wrk, Wrv, Wg, Wg + (size_t)HID * HID}};
        prep_wt_kernel<<<dim3(32, 32, 9), 256>>>(ws, wt);
    }
    cudaEventRecord(evFork, cudaStreamPerThread);
    cudaStreamWaitEvent(sB, evFork, 0);

    prep_rnd_kernel<<<SH / 4 / 256, 256>>>((const float4*)hs, (float4*)hs_t, SH / 4);

    // --- stream B: past prep + rk/rvt GEMM (independent of attn1 chain) ---
    prep_rnd_kernel<<<2 * SH / 4 / 256, 256, 0, sB>>>(
        (const float4*)past, (float4*)past_t, 2 * SH / 4);
    {
        GJ3 gj = {{{past_t, WT(5), brk, rk, 0, 0, 1, 0},
                   {past_t, WT(6), brv, 0, 0, rvt, 1, 0}, {}}};
        gemm_tt_kernel<<<dim3(8, 32, 2), 256, GSMEM3, sB>>>(gj, 2 * S_LEN, HID, HID);
    }
    cudaEventRecord(evJoin, sB);

    // --- main stream: self attention chain ---
    {
        GJ3 gj = {{{hs_t, WT(0), bq, q, 0, 0, 1, 0},
                   {hs_t, WT(1), bk, k, 0, 0, 1, 0},
                   {hs_t, WT(2), bv, 0, 0, vt, 1, 0}}};
        gemm_tt_kernel<<<dim3(8, 16, 3), 256, GSMEM3>>>(gj, S_LEN, HID, HID);
    }
    attn_t_kernel<<<dim3(16, 16, 1), 256, ATTN_SMEM>>>(q, k, vt, ctx_t, S_LEN);
    {
        GJ3 gj = {{{ctx_t, WT(3), bo, out, out_t, 0, 0, 0}, {}, {}}};
        gemm_tt_kernel<<<dim3(8, 16, 1), 256, GSMEM3>>>(gj, S_LEN, HID, HID);
    }
    {
        GJ3 gj = {{{out_t, WT(4), brq, rq, 0, 0, 1, 0}, {}, {}}};
        gemm_tt_kernel<<<dim3(8, 16, 1), 256, GSMEM3>>>(gj, S_LEN, HID, HID);
    }

    // --- join stream B, then recursive attention ---
    cudaStreamWaitEvent(cudaStreamPerThread, evJoin, 0);
    attn_t_kernel<<<dim3(16, 16, 2), 256, ATTN_SMEM>>>(rq, rk, rvt, rctx,
                                                       2 * S_LEN);
    combine_kernel<<<SH / 4 / 256, 256>>>((const float4*)rctx,
                                          (const float4*)(rctx + SH),
                                          (float4*)rec, (float4*)rec_t, SH / 4);

    // --- fused gate + blend -> d_out ---
    gemm_gate_kernel<<<dim3(8, 16), 256, GSMEM3>>>(out_t, rec_t, WT(7), WT(8), bg,
                                                   out, rec, (float*)d_out, HID);
}

// round 11
// speedup vs baseline: 1.1212x; 1.0146x over previous
#include <cuda_runtime.h>
#include <math.h>
#include <stdint.h>

// Problem constants
#define S_LEN 2048
#define HID   1024
#define NHEAD 16
#define HDIM  64
#define SH    (S_LEN * HID)
#define SCL2  0.1803368801111204f   // (1/sqrt(64)) * log2(e)
#define LOG2E 1.4426950408889634f

// ---------------------------------------------------------------------------
// Scratch
// ---------------------------------------------------------------------------
__device__ float g_wt[9 * HID * HID];   // 9 transposed tf32 weights [n][k]
__device__ float g_wo_r[HID * HID];     // Wo rounded (row-major, not transposed)
__device__ float g_wor_t[HID * HID];    // (Wo@Wrq)^T, tf32
__device__ float g_bor[HID];            // bo@Wrq + brq
__device__ float g_zero[HID];           // zeros (bias for W_or gemm)
__device__ float g_hs_t[SH];
__device__ float g_past_t[2 * SH];
__device__ float g_q[SH];
__device__ float g_k[SH];
__device__ float g_vt[SH];      // [NHEAD][HDIM][S_LEN]
__device__ float g_ctx_t[SH];
__device__ float g_out[SH];
__device__ float g_out_t[SH];
__device__ float g_gpre[SH];    // out_t @ Wg_lo + bg
__device__ float g_rq[SH];
__device__ float g_rk[2 * SH];
__device__ float g_rvt[2 * SH]; // [NHEAD][HDIM][2*S_LEN]
__device__ float g_rctx[2 * SH];
__device__ float g_rec[SH];
__device__ float g_rec_t[SH];

// ---------------------------------------------------------------------------
// helpers
// ---------------------------------------------------------------------------
__device__ __forceinline__ unsigned f2tf32(float x) {
    unsigned r;
    asm("cvt.rna.tf32.f32 %0, %1;" : "=r"(r) : "f"(x));
    return r;
}
__device__ __forceinline__ uint4 cvt4(float4 v) {
    uint4 r;
    r.x = f2tf32(v.x); r.y = f2tf32(v.y);
    r.z = f2tf32(v.z); r.w = f2tf32(v.w);
    return r;
}
__device__ __forceinline__ void mma8(float* c, const unsigned* a, const unsigned* b) {
    asm volatile(
        "mma.sync.aligned.m16n8k8.row.col.f32.tf32.tf32.f32 "
        "{%0,%1,%2,%3}, {%4,%5,%6,%7}, {%8,%9}, {%0,%1,%2,%3};\n"
        : "+f"(c[0]), "+f"(c[1]), "+f"(c[2]), "+f"(c[3])
        : "r"(a[0]), "r"(a[1]), "r"(a[2]), "r"(a[3]), "r"(b[0]), "r"(b[1]));
}
__device__ __forceinline__ void ldsm4(unsigned &r0, unsigned &r1,
                                      unsigned &r2, unsigned &r3, unsigned a) {
    asm volatile("ldmatrix.sync.aligned.m8n8.x4.shared.b16 {%0,%1,%2,%3}, [%4];"
        : "=r"(r0), "=r"(r1), "=r"(r2), "=r"(r3) : "r"(a));
}
__device__ __forceinline__ unsigned sptr(const void* p) {
    return (unsigned)__cvta_generic_to_shared(p);
}
__device__ __forceinline__ float ex2f(float x) {
    float y; asm("ex2.approx.ftz.f32 %0, %1;" : "=f"(y) : "f"(x)); return y;
}
#define CP_ASYNC16(dst, src) \
    asm volatile("cp.async.cg.shared.global [%0], [%1], 16;" :: "r"(dst), "l"(src) : "memory")
#define CP_COMMIT() asm volatile("cp.async.commit_group;" ::: "memory")
#define CP_WAIT0()  asm volatile("cp.async.wait_group 0;" ::: "memory")
#define CP_WAIT1()  asm volatile("cp.async.wait_group 1;" ::: "memory")

// ---------------------------------------------------------------------------
// Prep kernels
// ---------------------------------------------------------------------------
struct P9 { const float* p[9]; };

__global__ void __launch_bounds__(256) prep_wt_kernel(P9 ws, float* __restrict__ dst)
{
    __shared__ float t[32][33];
    const float* __restrict__ src = ws.p[blockIdx.z];
    float* __restrict__ d = dst + (size_t)blockIdx.z * HID * HID;
    const int r0 = blockIdx.y * 32, c0 = blockIdx.x * 32;
    const int lr = threadIdx.x >> 3, lc = (threadIdx.x & 7) * 4;

    float4 v = *(const float4*)&src[(size_t)(r0 + lr) * HID + c0 + lc];
    t[lr][lc] = v.x; t[lr][lc + 1] = v.y; t[lr][lc + 2] = v.z; t[lr][lc + 3] = v.w;
    __syncthreads();

    uint4 w;
    w.x = f2tf32(t[lc + 0][lr]);
    w.y = f2tf32(t[lc + 1][lr]);
    w.z = f2tf32(t[lc + 2][lr]);
    w.w = f2tf32(t[lc + 3][lr]);
    *(uint4*)&d[(size_t)(c0 + lr) * HID + r0 + lc] = w;
}

__global__ void prep_rnd_kernel(const float4* __restrict__ s,
                                float4* __restrict__ d, int n4)
{
    int i = blockIdx.x * blockDim.x + threadIdx.x;
    if (i < n4) *(uint4*)&d[i] = cvt4(s[i]);
}

// b_or[j] = sum_i bo[i] * Wrq[i][j] + brq[j]
__global__ void __launch_bounds__(256) bor_kernel(
    const float* __restrict__ bo, const float* __restrict__ Wrq,
    const float* __restrict__ brq, float* __restrict__ bor)
{
    int j = blockIdx.x * blockDim.x + threadIdx.x;
    float s = brq[j];
    for (int i = 0; i < HID; i++)
        s += bo[i] * Wrq[(size_t)i * HID + j];
    bor[j] = s;
}

// ---------------------------------------------------------------------------
// GEMM: C[M,N] = A[M,K] @ Bt[N,K]^T + bias. 128x128 tile, BK=32, 8 warps
// (warp tile 64x32). 3-stage cp.async ring, ldmatrix fragments.
// C optional; C2 = extra tf32 copy; CT = transposed copy ct[c*M + r].
// ---------------------------------------------------------------------------
#define TPX 36
#define STG_WORDS ((128 + 128) * TPX)
#define GSMEM3 (3 * STG_WORDS * 4)

struct GJob { const float* A; const float* Bt; const float* bias;
              float* C; float* C2; float* CT; int rnd; int pad; };
struct GJ3 { GJob j[3]; };

__global__ void __launch_bounds__(256, 2) gemm_tt_kernel(GJ3 gj, int M, int N, int K)
{
    extern __shared__ unsigned sm[];
    const GJob jb = gj.j[blockIdx.z];

    const int tid  = threadIdx.x;
    const int warp = tid >> 5;
    const int lane = tid & 31;
    const int m0 = blockIdx.y * 128;
    const int n0 = blockIdx.x * 128;
    const int wm0 = (warp >> 2) * 64;
    const int wn0 = (warp & 3) * 32;

    const int srow = tid >> 1;
    const int scol = (tid & 1) * 16;
    const float* Ag = jb.A  + (size_t)(m0 + srow) * K + scol;
    const float* Bg = jb.Bt + (size_t)(n0 + srow) * K + scol;
    const unsigned smb = sptr(sm);
    const unsigned sa = smb + (srow * TPX + scol) * 4;
    const unsigned sb = smb + (128 * TPX + srow * TPX + scol) * 4;

    const int lr  = (lane & 7) + ((lane >> 3) & 1) * 8;
    const int lc  = ((lane >> 4) & 1) * 4;
    const int brr = ((lane >> 4) & 1) * 8 + (lane & 7);
    const int bcc = ((lane >> 3) & 1) * 4;

    float acc[4][4][4];
    #pragma unroll
    for (int mt = 0; mt < 4; mt++)
        #pragma unroll
        for (int nt = 0; nt < 4; nt++)
            #pragma unroll
            for (int i = 0; i < 4; i++) acc[mt][nt][i] = 0.0f;

    const int T = K / 32;
    auto issue = [&](int st) {
        if (st < T) {
            const unsigned off = (unsigned)((st % 3) * STG_WORDS) * 4;
            const int ko = st * 32;
            #pragma unroll
            for (int i = 0; i < 4; i++) CP_ASYNC16(sa + off + i * 16, Ag + ko + i * 4);
            #pragma unroll
            for (int i = 0; i < 4; i++) CP_ASYNC16(sb + off + i * 16, Bg + ko + i * 4);
        }
        CP_COMMIT();
    };

    issue(0);
    issue(1);

    for (int t = 0; t < T; t++) {
        CP_WAIT1();
        __syncthreads();
        issue(t + 2);

        const unsigned so = (unsigned)((t % 3) * STG_WORDS);
        const unsigned ab = smb + (so + (wm0 + lr) * TPX + lc) * 4;
        const unsigned bb = smb + (so + 128 * TPX + (wn0 + brr) * TPX + bcc) * 4;
        #pragma unroll
        for (int ks = 0; ks < 4; ks++) {
            unsigned a[4][4];
            #pragma unroll
            for (int mt = 0; mt < 4; mt++)
                ldsm4(a[mt][0], a[mt][1], a[mt][2], a[mt][3],
                      ab + (unsigned)(mt * 16 * TPX + ks * 8) * 4);
            #pragma unroll
            for (int ntp = 0; ntp < 2; ntp++) {
                unsigned b0, b1, b2, b3;
                ldsm4(b0, b1, b2, b3, bb + (unsigned)(ntp * 16 * TPX + ks * 8) * 4);
                unsigned ba[2] = {b0, b1}, bx[2] = {b2, b3};
                #pragma unroll
                for (int mt = 0; mt < 4; mt++) {
                    mma8(acc[mt][2 * ntp],     a[mt], ba);
                    mma8(acc[mt][2 * ntp + 1], a[mt], bx);
                }
            }
        }
        __syncthreads();
    }

    #pragma unroll
    for (int mt = 0; mt < 4; mt++) {
        #pragma unroll
        for (int nt = 0; nt < 4; nt++) {
            int r0 = m0 + wm0 + mt * 16 + (lane >> 2);
            int c0 = n0 + wn0 + nt * 8 + 2 * (lane & 3);
            float b0 = jb.bias[c0], b1 = jb.bias[c0 + 1];
            float v0 = acc[mt][nt][0] + b0, v1 = acc[mt][nt][1] + b1;
            float v2 = acc[mt][nt][2] + b0, v3 = acc[mt][nt][3] + b1;
            size_t p0 = (size_t)r0 * N + c0;
            size_t p1 = (size_t)(r0 + 8) * N + c0;
            if (jb.C2) {
                uint2 u0 = {f2tf32(v0), f2tf32(v1)};
                uint2 u1 = {f2tf32(v2), f2tf32(v3)};
                *(uint2*)&jb.C2[p0] = u0;
                *(uint2*)&jb.C2[p1] = u1;
            }
            if (jb.rnd) {
                v0 = __uint_as_float(f2tf32(v0));
                v1 = __uint_as_float(f2tf32(v1));
                v2 = __uint_as_float(f2tf32(v2));
                v3 = __uint_as_float(f2tf32(v3));
            }
            if (jb.CT) {
                jb.CT[(size_t)c0 * M + r0]           = v0;
                jb.CT[(size_t)(c0 + 1) * M + r0]     = v1;
                jb.CT[(size_t)c0 * M + r0 + 8]       = v2;
                jb.CT[(size_t)(c0 + 1) * M + r0 + 8] = v3;
            }
            if (jb.C) {
                float2 w0 = {v0, v1}, w1 = {v2, v3};
                *(float2*)&jb.C[p0] = w0;
                *(float2*)&jb.C[p1] = w1;
            }
        }
    }
}

// ---------------------------------------------------------------------------
// Final gate GEMM: gpre = gph + rec_t @ WgT_hi^T (K=1024), then
// dst = out + sigmoid(gpre) * (rec - out). gph = out_t@Wg_lo + bg, precomputed.
// ---------------------------------------------------------------------------
__global__ void __launch_bounds__(256, 2) gate_fin_kernel(
    const float* __restrict__ recT, const float* __restrict__ WgT_hi,
    const float* __restrict__ gph,
    const float* __restrict__ outF, const float* __restrict__ recF,
    float* __restrict__ dst, int N)
{
    extern __shared__ unsigned sm[];

    const int tid  = threadIdx.x;
    const int warp = tid >> 5;
    const int lane = tid & 31;
    const int m0 = blockIdx.y * 128;
    const int n0 = blockIdx.x * 128;
    const int wm0 = (warp >> 2) * 64;
    const int wn0 = (warp & 3) * 32;

    const int srow = tid >> 1;
    const int scol = (tid & 1) * 16;
    const float* Ag = recT  + (size_t)(m0 + srow) * HID + scol;
    const float* Bg = WgT_hi + (size_t)(n0 + srow) * HID + scol;
    const unsigned smb = sptr(sm);
    const unsigned sa = smb + (srow * TPX + scol) * 4;
    const unsigned sb = smb + (128 * TPX + srow * TPX + scol) * 4;

    const int lr  = (lane & 7) + ((lane >> 3) & 1) * 8;
    const int lc  = ((lane >> 4) & 1) * 4;
    const int brr = ((lane >> 4) & 1) * 8 + (lane & 7);
    const int bcc = ((lane >> 3) & 1) * 4;

    float acc[4][4][4];
    #pragma unroll
    for (int mt = 0; mt < 4; mt++)
        #pragma unroll
        for (int nt = 0; nt < 4; nt++)
            #pragma unroll
            for (int i = 0; i < 4; i++) acc[mt][nt][i] = 0.0f;

    const int T = HID / 32;
    auto issue = [&](int st) {
        if (st < T) {
            const unsigned off = (unsigned)((st % 3) * STG_WORDS) * 4;
            const int ko = st * 32;
            #pragma unroll
            for (int i = 0; i < 4; i++) CP_ASYNC16(sa + off + i * 16, Ag + ko + i * 4);
            #pragma unroll
            for (int i = 0; i < 4; i++) CP_ASYNC16(sb + off + i * 16, Bg + ko + i * 4);
        }
        CP_COMMIT();
    };

    issue(0);
    issue(1);

    for (int t = 0; t < T; t++) {
        CP_WAIT1();
        __syncthreads();
        issue(t + 2);

        const unsigned so = (unsigned)((t % 3) * STG_WORDS);
        const unsigned ab = smb + (so + (wm0 + lr) * TPX + lc) * 4;
        const unsigned bb = smb + (so + 128 * TPX + (wn0 + brr) * TPX + bcc) * 4;
        #pragma unroll
        for (int ks = 0; ks < 4; ks++) {
            unsigned a[4][4];
            #pragma unroll
            for (int mt = 0; mt < 4; mt++)
                ldsm4(a[mt][0], a[mt][1], a[mt][2], a[mt][3],
                      ab + (unsigned)(mt * 16 * TPX + ks * 8) * 4);
            #pragma unroll
            for (int ntp = 0; ntp < 2; ntp++) {
                unsigned b0, b1, b2, b3;
                ldsm4(b0, b1, b2, b3, bb + (unsigned)(ntp * 16 * TPX + ks * 8) * 4);
                unsigned ba[2] = {b0, b1}, bx[2] = {b2, b3};
                #pragma unroll
                for (int mt = 0; mt < 4; mt++) {
                    mma8(acc[mt][2 * ntp],     a[mt], ba);
                    mma8(acc[mt][2 * ntp + 1], a[mt], bx);
                }
            }
        }
        __syncthreads();
    }

    #pragma unroll
    for (int mt = 0; mt < 4; mt++) {
        #pragma unroll
        for (int nt = 0; nt < 4; nt++) {
            int r0 = m0 + wm0 + mt * 16 + (lane >> 2);
            int c0 = n0 + wn0 + nt * 8 + 2 * (lane & 3);
            size_t p0 = (size_t)r0 * N + c0;
            size_t p1 = (size_t)(r0 + 8) * N + c0;
            float2 h0 = *(const float2*)&gph[p0];
            float2 h1 = *(const float2*)&gph[p1];
            float gp0 = acc[mt][nt][0] + h0.x, gp1 = acc[mt][nt][1] + h0.y;
            float gp2 = acc[mt][nt][2] + h1.x, gp3 = acc[mt][nt][3] + h1.y;
            float2 o0 = *(const float2*)&outF[p0];
            float2 o1 = *(const float2*)&outF[p1];
            float2 rc0 = *(const float2*)&recF[p0];
            float2 rc1 = *(const float2*)&recF[p1];
            float gg0 = 1.0f / (1.0f + ex2f(-gp0 * LOG2E));
            float gg1 = 1.0f / (1.0f + ex2f(-gp1 * LOG2E));
            float gg2 = 1.0f / (1.0f + ex2f(-gp2 * LOG2E));
            float gg3 = 1.0f / (1.0f + ex2f(-gp3 * LOG2E));
            float2 w0 = {o0.x + gg0 * (rc0.x - o0.x), o0.y + gg1 * (rc0.y - o0.y)};
            float2 w1 = {o1.x + gg2 * (rc1.x - o1.x), o1.y + gg3 * (rc1.y - o1.y)};
            *(float2*)&dst[p0] = w0;
            *(float2*)&dst[p1] = w1;
        }
    }
}

// ---------------------------------------------------------------------------
// Flash attention v4 (unchanged from round 10): V pre-transposed in global.
// ---------------------------------------------------------------------------
#define PW 68
#define ATTN_WORDS ((128 + 128 + 128) * PW)   // QP + 2xK + 2xVt
#define ATTN_SMEM  (ATTN_WORDS * 4)

__global__ void __launch_bounds__(256, 2) attn_t_kernel(
    const float* __restrict__ Q, const float* __restrict__ K,
    const float* __restrict__ Vt, float* __restrict__ O, int Mv)
{
    extern __shared__ unsigned sm[];
    unsigned* QP = sm;
    unsigned* KB = sm + 128 * PW;
    unsigned* VB = sm + 256 * PW;

    const size_t zoff = (size_t)blockIdx.z * SH;
    K += zoff; O += zoff;

    const int tid  = threadIdx.x;
    const int warp = tid >> 5;
    const int lane = tid & 31;
    const int hoff = blockIdx.y * HDIM;
    const int q0   = blockIdx.x * 128;

    const float* Vtb = Vt + (size_t)hoff * Mv + (size_t)blockIdx.z * S_LEN;

    const int lr  = (lane & 7) + ((lane >> 3) & 1) * 8;
    const int lc  = ((lane >> 4) & 1) * 4;
    const int brr = ((lane >> 4) & 1) * 8 + (lane & 7);
    const int bcc = ((lane >> 3) & 1) * 4;

    const int krow = tid >> 2;
    const int kcol = (tid & 3) * 16;

    {
        const int row = tid >> 1, half = tid & 1;
        const uint4* Qg = (const uint4*)(Q + (size_t)(q0 + row) * HID + hoff) + half * 8;
        uint4* Qs = (uint4*)&QP[row * PW + half * 32];
        #pragma unroll
        for (int j = 0; j < 8; j++) Qs[j] = Qg[j];
    }

    auto issueKV = [&](int s) {
        const unsigned bo = (unsigned)((s & 1) * 64 * PW);
        unsigned kd = sptr(&KB[bo + krow * PW + kcol]);
        const float* kg = K + (size_t)(s * 64 + krow) * HID + hoff + kcol;
        #pragma unroll
        for (int i = 0; i < 4; i++) CP_ASYNC16(kd + i * 16, kg + i * 4);
        unsigned vd = sptr(&VB[bo + krow * PW + kcol]);
        const float* vg = Vtb + (size_t)krow * Mv + s * 64 + kcol;
        #pragma unroll
        for (int i = 0; i < 4; i++) CP_ASYNC16(vd + i * 16, vg + i * 4);
    };

    issueKV(0);
    CP_COMMIT();
    __syncthreads();

    unsigned qa[8][4];
    {
        unsigned base = sptr(&QP[(warp * 16 + lr) * PW + lc]);
        #pragma unroll
        for (int g = 0; g < 8; g++)
            ldsm4(qa[g][0], qa[g][1], qa[g][2], qa[g][3], base + g * 32);
    }

    float o[8][4];
    #pragma unroll
    for (int nt = 0; nt < 8; nt++)
        #pragma unroll
        for (int i = 0; i < 4; i++) o[nt][i] = 0.0f;
    float mrow0 = -1e30f, mrow1 = -1e30f, lrow0 = 0.0f, lrow1 = 0.0f;

    const unsigned pbase  = sptr(&QP[(warp * 16 + lr) * PW + lc]);
    const unsigned kbase0 = sptr(KB) + (unsigned)(brr * PW + bcc) * 4;
    const unsigned vbase0 = sptr(VB) + (unsigned)(brr * PW + bcc) * 4;

    const int T = S_LEN / 64;
    for (int tile = 0; tile < T; tile++) {
        CP_WAIT0();
        __syncthreads();
        if (tile + 1 < T) issueKV(tile + 1);
        CP_COMMIT();

        const unsigned so = (unsigned)((tile & 1) * 64 * PW) * 4;

        float s[8][4];
        #pragma unroll
        for (int nt = 0; nt < 8; nt++)
            #pragma unroll
            for (int i = 0; i < 4; i++) s[nt][i] = 0.0f;

        {
            const unsigned kbase = kbase0 + so;
            #pragma unroll
            for (int g = 0; g < 8; g++) {
                #pragma unroll
                for (int ntp = 0; ntp < 4; ntp++) {
                    unsigned b0, b1, b2, b3;
                    ldsm4(b0, b1, b2, b3, kbase + (unsigned)(ntp * 16 * PW + g * 8) * 4);
                    unsigned ba[2] = {b0, b1}, bb[2] = {b2, b3};
                    mma8(s[2 * ntp],     qa[g], ba);
                    mma8(s[2 * ntp + 1], qa[g], bb);
                }
            }
        }

        float mx0 = -1e30f, mx1 = -1e30f;
        #pragma unroll
        for (int nt = 0; nt < 8; nt++) {
            s[nt][0] *= SCL2; s[nt][1] *= SCL2;
            s[nt][2] *= SCL2; s[nt][3] *= SCL2;
            mx0 = fmaxf(mx0, fmaxf(s[nt][0], s[nt][1]));
            mx1 = fmaxf(mx1, fmaxf(s[nt][2], s[nt][3]));
        }
        mx0 = fmaxf(mx0, __shfl_xor_sync(0xffffffffu, mx0, 1));
        mx0 = fmaxf(mx0, __shfl_xor_sync(0xffffffffu, mx0, 2));
        mx1 = fmaxf(mx1, __shfl_xor_sync(0xffffffffu, mx1, 1));
        mx1 = fmaxf(mx1, __shfl_xor_sync(0xffffffffu, mx1, 2));

        float mn0 = fmaxf(mrow0, mx0);
        float mn1 = fmaxf(mrow1, mx1);
        float a0 = ex2f(mrow0 - mn0);
        float a1 = ex2f(mrow1 - mn1);

        {
            const int pr = lane >> 2;
            const int pc = 2 * (lane & 3);
            unsigned* P0 = &QP[(warp * 16 + pr) * PW + pc];
            unsigned* P1 = &QP[(warp * 16 + pr + 8) * PW + pc];
            float rs0 = 0.0f, rs1 = 0.0f;
            #pragma unroll
            for (int nt = 0; nt < 8; nt++) {
                float p0 = ex2f(s[nt][0] - mn0);
                float p1 = ex2f(s[nt][1] - mn0);
                float p2 = ex2f(s[nt][2] - mn1);
                float p3 = ex2f(s[nt][3] - mn1);
                rs0 += p0 + p1;
                rs1 += p2 + p3;
                uint2 w0 = {f2tf32(p0), f2tf32(p1)};
                uint2 w1 = {f2tf32(p2), f2tf32(p3)};
                *(uint2*)(P0 + nt * 8) = w0;
                *(uint2*)(P1 + nt * 8) = w1;
            }
            rs0 += __shfl_xor_sync(0xffffffffu, rs0, 1);
            rs0 += __shfl_xor_sync(0xffffffffu, rs0, 2);
            rs1 += __shfl_xor_sync(0xffffffffu, rs1, 1);
            rs1 += __shfl_xor_sync(0xffffffffu, rs1, 2);
            lrow0 = lrow0 * a0 + rs0;
            lrow1 = lrow1 * a1 + rs1;
            mrow0 = mn0; mrow1 = mn1;
        }
        #pragma unroll
        for (int nt = 0; nt < 8; nt++) {
            o[nt][0] *= a0; o[nt][1] *= a0;
            o[nt][2] *= a1; o[nt][3] *= a1;
        }
        __syncwarp();

        {
            const unsigned vbase = vbase0 + so;
            #pragma unroll
            for (int g = 0; g < 8; g++) {
                unsigned pa[4];
                ldsm4(pa[0], pa[1], pa[2], pa[3], pbase + g * 32);
                #pragma unroll
                for (int ntp = 0; ntp < 4; ntp++) {
                    unsigned b0, b1, b2, b3;
                    ldsm4(b0, b1, b2, b3, vbase + (unsigned)(ntp * 16 * PW + g * 8) * 4);
                    unsigned ba[2] = {b0, b1}, bb[2] = {b2, b3};
                    mma8(o[2 * ntp],     pa, ba);
                    mma8(o[2 * ntp + 1], pa, bb);
                }
            }
        }
    }

    float i0 = 1.0f / lrow0;
    float i1 = 1.0f / lrow1;
    int r0 = q0 + warp * 16 + (lane >> 2);
    #pragma unroll
    for (int nt = 0; nt < 8; nt++) {
        int c = hoff + nt * 8 + 2 * (lane & 3);
        uint2 v0 = {f2tf32(o[nt][0] * i0), f2tf32(o[nt][1] * i0)};
        uint2 v1 = {f2tf32(o[nt][2] * i1), f2tf32(o[nt][3] * i1)};
        *(uint2*)&O[(size_t)r0 * HID + c] = v0;
        *(uint2*)&O[(size_t)(r0 + 8) * HID + c] = v1;
    }
}

// ---------------------------------------------------------------------------
// Combine: rec = 0.5*(a+b) in fp32 and tf32 copies
// ---------------------------------------------------------------------------
__global__ void combine_kernel(const float4* __restrict__ a,
                               const float4* __restrict__ b,
                               float4* __restrict__ oF,
                               float4* __restrict__ oT, int n4)
{
    int i = blockIdx.x * blockDim.x + threadIdx.x;
    if (i < n4) {
        float4 x = a[i], y = b[i], r;
        r.x = 0.5f * (x.x + y.x); r.y = 0.5f * (x.y + y.y);
        r.z = 0.5f * (x.z + y.z); r.w = 0.5f * (x.w + y.w);
        oF[i] = r;
        *(uint4*)&oT[i] = cvt4(r);
    }
}

// ---------------------------------------------------------------------------
// Launch — dual-stream fork/join with weight-product fusion and gate split.
// ---------------------------------------------------------------------------
extern "C" void kernel_launch(void* const* d_in, const int* in_sizes, int n_in,
                              void* d_out, int out_size)
{
    (void)in_sizes; (void)n_in; (void)out_size;

    const float* hs   = (const float*)d_in[0];
    const float* past = (const float*)d_in[1];
    const float* Wq = (const float*)d_in[2];  const float* bq = (const float*)d_in[3];
    const float* Wk = (const float*)d_in[4];  const float* bk = (const float*)d_in[5];
    const float* Wv = (const float*)d_in[6];  const float* bv = (const float*)d_in[7];
    const float* Wo = (const float*)d_in[8];  const float* bo = (const float*)d_in[9];
    const float* Wrq = (const float*)d_in[10]; const float* brq = (const float*)d_in[11];
    const float* Wrk = (const float*)d_in[12]; const float* brk = (const float*)d_in[13];
    const float* Wrv = (const float*)d_in[14]; const float* brv = (const float*)d_in[15];
    const float* Wg = (const float*)d_in[16];  const float* bg = (const float*)d_in[17];

    float *wt, *wo_r, *wor_t, *bor, *zero, *hs_t, *past_t, *q, *k, *vt, *ctx_t,
          *out, *out_t, *gpre, *rq, *rk, *rvt, *rctx, *rec, *rec_t;
    cudaGetSymbolAddress((void**)&wt,     g_wt);
    cudaGetSymbolAddress((void**)&wo_r,   g_wo_r);
    cudaGetSymbolAddress((void**)&wor_t,  g_wor_t);
    cudaGetSymbolAddress((void**)&bor,    g_bor);
    cudaGetSymbolAddress((void**)&zero,   g_zero);
    cudaGetSymbolAddress((void**)&hs_t,   g_hs_t);
    cudaGetSymbolAddress((void**)&past_t, g_past_t);
    cudaGetSymbolAddress((void**)&q,      g_q);
    cudaGetSymbolAddress((void**)&k,      g_k);
    cudaGetSymbolAddress((void**)&vt,     g_vt);
    cudaGetSymbolAddress((void**)&ctx_t,  g_ctx_t);
    cudaGetSymbolAddress((void**)&out,    g_out);
    cudaGetSymbolAddress((void**)&out_t,  g_out_t);
    cudaGetSymbolAddress((void**)&gpre,   g_gpre);
    cudaGetSymbolAddress((void**)&rq,     g_rq);
    cudaGetSymbolAddress((void**)&rk,     g_rk);
    cudaGetSymbolAddress((void**)&rvt,    g_rvt);
    cudaGetSymbolAddress((void**)&rctx,   g_rctx);
    cudaGetSymbolAddress((void**)&rec,    g_rec);
    cudaGetSymbolAddress((void**)&rec_t,  g_rec_t);

    cudaFuncSetAttribute(attn_t_kernel,
                         cudaFuncAttributeMaxDynamicSharedMemorySize, ATTN_SMEM);
    cudaFuncSetAttribute(gemm_tt_kernel,
                         cudaFuncAttributeMaxDynamicSharedMemorySize, GSMEM3);
    cudaFuncSetAttribute(gate_fin_kernel,
                         cudaFuncAttributeMaxDynamicSharedMemorySize, GSMEM3);

    cudaStream_t sB;
    cudaStreamCreateWithFlags(&sB, cudaStreamNonBlocking);
    cudaEvent_t evFork, evWor, evJoin, evOut, evGp;
    cudaEventCreateWithFlags(&evFork, cudaEventDisableTiming);
    cudaEventCreateWithFlags(&evWor,  cudaEventDisableTiming);
    cudaEventCreateWithFlags(&evJoin, cudaEventDisableTiming);
    cudaEventCreateWithFlags(&evOut,  cudaEventDisableTiming);
    cudaEventCreateWithFlags(&evGp,   cudaEventDisableTiming);

    #define WT(i) (wt + (size_t)(i) * HID * HID)

    // --- prep (main stream): weight transpose ---
    {
        P9 ws = {{Wq, Wk, Wv, Wo, Wrq, Wrk, Wrv, Wg, Wg + (size_t)HID * HID}};
        prep_wt_kernel<<<dim3(32, 32, 9), 256>>>(ws, wt);
    }
    cudaEventRecord(evFork, cudaStreamPerThread);
    cudaStreamWaitEvent(sB, evFork, 0);

    prep_rnd_kernel<<<SH / 4 / 256, 256>>>((const float4*)hs, (float4*)hs_t, SH / 4);

    // --- stream B: past prep, W_or = Wo@Wrq fusion, b_or, rk/rvt GEMM ---
    prep_rnd_kernel<<<2 * SH / 4 / 256, 256, 0, sB>>>(
        (const float4*)past, (float4*)past_t, 2 * SH / 4);
    prep_rnd_kernel<<<HID * HID / 4 / 256, 256, 0, sB>>>(
        (const float4*)Wo, (float4*)wo_r, HID * HID / 4);
    {
        // wor_t[j][k] = sum_i WrqT[j][i] * Wo[k][i]  (=(Wo@Wrq)^T), tf32-rounded
        GJ3 gj = {{{WT(4), wo_r, zero, wor_t, 0, 0, 1, 0}, {}, {}}};
        gemm_tt_kernel<<<dim3(8, 8, 1), 256, GSMEM3, sB>>>(gj, HID, HID, HID);
    }
    bor_kernel<<<HID / 256, 256, 0, sB>>>(bo, Wrq, brq, bor);
    cudaEventRecord(evWor, sB);
    {
        GJ3 gj = {{{past_t, WT(5), brk, rk, 0, 0, 1, 0},
                   {past_t, WT(6), brv, 0, 0, rvt, 1, 0}, {}}};
        gemm_tt_kernel<<<dim3(8, 32, 2), 256, GSMEM3, sB>>>(gj, 2 * S_LEN, HID, HID);
    }
    cudaEventRecord(evJoin, sB);

    // --- main stream: self attention chain ---
    {
        GJ3 gj = {{{hs_t, WT(0), bq, q, 0, 0, 1, 0},
                   {hs_t, WT(1), bk, k, 0, 0, 1, 0},
                   {hs_t, WT(2), bv, 0, 0, vt, 1, 0}}};
        gemm_tt_kernel<<<dim3(8, 16, 3), 256, GSMEM3>>>(gj, S_LEN, HID, HID);
    }
    attn_t_kernel<<<dim3(16, 16, 1), 256, ATTN_SMEM>>>(q, k, vt, ctx_t, S_LEN);

    // Wo and rq GEMMs concurrently (both depend only on ctx_t)
    cudaStreamWaitEvent(cudaStreamPerThread, evWor, 0);
    {
        GJ3 gj = {{{ctx_t, WT(3), bo, out, out_t, 0, 0, 0},
                   {ctx_t, wor_t, bor, rq, 0, 0, 1, 0}, {}}};
        gemm_tt_kernel<<<dim3(8, 16, 2), 256, GSMEM3>>>(gj, S_LEN, HID, HID);
    }
    cudaEventRecord(evOut, cudaStreamPerThread);

    // --- stream B: gpre_half = out_t @ Wg_lo + bg (overlaps attn2) ---
    cudaStreamWaitEvent(sB, evOut, 0);
    {
        GJ3 gj = {{{out_t, WT(7), bg, gpre, 0, 0, 0, 0}, {}, {}}};
        gemm_tt_kernel<<<dim3(8, 16, 1), 256, GSMEM3, sB>>>(gj, S_LEN, HID, HID);
    }
    cudaEventRecord(evGp, sB);

    // --- main stream: recursive attention ---
    cudaStreamWaitEvent(cudaStreamPerThread, evJoin, 0);
    attn_t_kernel<<<dim3(16, 16, 2), 256, ATTN_SMEM>>>(rq, rk, rvt, rctx,
                                                       2 * S_LEN);
    combine_kernel<<<SH / 4 / 256, 256>>>((const float4*)rctx,
                                          (const float4*)(rctx + SH),
                                          (float4*)rec, (float4*)rec_t, SH / 4);

    // --- final gate (rec half) + blend -> d_out ---
    cudaStreamWaitEvent(cudaStreamPerThread, evGp, 0);
    gate_fin_kernel<<<dim3(8, 16), 256, GSMEM3>>>(rec_t, WT(8), gpre,
                                                  out, rec, (float*)d_out, HID);
}

// round 12
// speedup vs baseline: 1.8491x; 1.6492x over previous
#include <cuda_runtime.h>
#include <cuda_fp16.h>
#include <math.h>
#include <stdint.h>

// Problem constants
#define S_LEN 2048
#define HID   1024
#define NHEAD 16
#define HDIM  64
#define SH    (S_LEN * HID)
#define SCL2  0.1803368801111204f   // (1/sqrt(64)) * log2(e)
#define LOG2E 1.4426950408889634f

// ---------------------------------------------------------------------------
// Scratch (fp16 operands, fp32 where consumed by the final blend)
// ---------------------------------------------------------------------------
__device__ __half g_wt[9 * HID * HID];   // 9 transposed fp16 weights [n][k]
__device__ __half g_wo_h[HID * HID];     // Wo fp16 (row-major)
__device__ __half g_wor_t[HID * HID];    // (Wo@Wrq)^T fp16
__device__ float  g_bor[HID];            // bo@Wrq + brq
__device__ float  g_zero[HID];
__device__ __half g_hs_h[SH];
__device__ __half g_past_h[2 * SH];
__device__ __half g_q[SH];
__device__ __half g_k[SH];
__device__ __half g_vt[SH];              // [NHEAD][HDIM][S_LEN]
__device__ __half g_ctx_h[SH];
__device__ float  g_out[SH];
__device__ __half g_out_h[SH];
__device__ float  g_gpre[SH];
__device__ __half g_rq[SH];
__device__ __half g_rk[2 * SH];
__device__ __half g_rvt[2 * SH];         // [NHEAD][HDIM][2*S_LEN]
__device__ __half g_rctx[2 * SH];
__device__ float  g_rec[SH];
__device__ __half g_rec_h[SH];

// ---------------------------------------------------------------------------
// helpers
// ---------------------------------------------------------------------------
__device__ __forceinline__ unsigned f22h2(float lo, float hi) {
    __half2 h = __floats2half2_rn(lo, hi);
    return *(unsigned*)&h;
}
__device__ __forceinline__ void mmah(float* c, const unsigned* a, const unsigned* b) {
    asm volatile(
        "mma.sync.aligned.m16n8k16.row.col.f32.f16.f16.f32 "
        "{%0,%1,%2,%3}, {%4,%5,%6,%7}, {%8,%9}, {%0,%1,%2,%3};\n"
        : "+f"(c[0]), "+f"(c[1]), "+f"(c[2]), "+f"(c[3])
        : "r"(a[0]), "r"(a[1]), "r"(a[2]), "r"(a[3]), "r"(b[0]), "r"(b[1]));
}
__device__ __forceinline__ void ldsm4(unsigned &r0, unsigned &r1,
                                      unsigned &r2, unsigned &r3, unsigned a) {
    asm volatile("ldmatrix.sync.aligned.m8n8.x4.shared.b16 {%0,%1,%2,%3}, [%4];"
        : "=r"(r0), "=r"(r1), "=r"(r2), "=r"(r3) : "r"(a));
}
__device__ __forceinline__ unsigned sptr(const void* p) {
    return (unsigned)__cvta_generic_to_shared(p);
}
__device__ __forceinline__ float ex2f(float x) {
    float y; asm("ex2.approx.ftz.f32 %0, %1;" : "=f"(y) : "f"(x)); return y;
}
#define CP_ASYNC16(dst, src) \
    asm volatile("cp.async.cg.shared.global [%0], [%1], 16;" :: "r"(dst), "l"(src) : "memory")
#define CP_COMMIT() asm volatile("cp.async.commit_group;" ::: "memory")
#define CP_WAIT0()  asm volatile("cp.async.wait_group 0;" ::: "memory")
#define CP_WAIT1()  asm volatile("cp.async.wait_group 1;" ::: "memory")

// ---------------------------------------------------------------------------
// Prep kernels
// ---------------------------------------------------------------------------
struct P9 { const float* p[9]; };

// Transpose + convert weights: dst[z][n][k] = h(src[z][k][n])
__global__ void __launch_bounds__(256) prep_wt_kernel(P9 ws, __half* __restrict__ dst)
{
    __shared__ float t[32][33];
    const float* __restrict__ src = ws.p[blockIdx.z];
    __half* __restrict__ d = dst + (size_t)blockIdx.z * HID * HID;
    const int r0 = blockIdx.y * 32, c0 = blockIdx.x * 32;
    const int lr = threadIdx.x >> 3, lc = (threadIdx.x & 7) * 4;

    float4 v = *(const float4*)&src[(size_t)(r0 + lr) * HID + c0 + lc];
    t[lr][lc] = v.x; t[lr][lc + 1] = v.y; t[lr][lc + 2] = v.z; t[lr][lc + 3] = v.w;
    __syncthreads();

    uint2 w;
    w.x = f22h2(t[lc + 0][lr], t[lc + 1][lr]);
    w.y = f22h2(t[lc + 2][lr], t[lc + 3][lr]);
    *(uint2*)&d[(size_t)(c0 + lr) * HID + r0 + lc] = w;
}

// fp32 -> fp16 elementwise
__global__ void prep_h_kernel(const float4* __restrict__ s,
                              uint2* __restrict__ d, int n4)
{
    int i = blockIdx.x * blockDim.x + threadIdx.x;
    if (i < n4) {
        float4 v = s[i];
        uint2 w = {f22h2(v.x, v.y), f22h2(v.z, v.w)};
        d[i] = w;
    }
}

// b_or[j] = sum_i bo[i] * Wrq[i][j] + brq[j]
__global__ void __launch_bounds__(256) bor_kernel(
    const float* __restrict__ bo, const float* __restrict__ Wrq,
    const float* __restrict__ brq, float* __restrict__ bor)
{
    int j = blockIdx.x * blockDim.x + threadIdx.x;
    float s = brq[j];
    for (int i = 0; i < HID; i++)
        s += bo[i] * Wrq[(size_t)i * HID + j];
    bor[j] = s;
}

// ---------------------------------------------------------------------------
// fp16 GEMM: C[M,N] = A[M,K] @ Bt[N,K]^T + bias. 128x128 tile, BK=64,
// 8 warps (warp 64x32), 3-stage cp.async, ldmatrix fp16 fragments.
// Outputs: C (fp32, opt), CH (fp16 [M][N], opt), CT (fp16 [N][M], opt).
// ---------------------------------------------------------------------------
#define APH 72                       // halves pitch (64 + 8); 144B rows
#define APB (APH * 2)
#define STGH ((128 + 128) * APH)     // halves per stage
#define GSMEMH (3 * STGH * 2)        // 110,592 bytes

struct GJob { const __half* A; const __half* Bt; const float* bias;
              float* C; __half* CH; __half* CT; };
struct GJ3 { GJob j[3]; };

__global__ void __launch_bounds__(256, 2) gemm_h_kernel(GJ3 gj, int M, int N, int K)
{
    extern __shared__ unsigned sm[];
    const GJob jb = gj.j[blockIdx.z];

    const int tid  = threadIdx.x;
    const int warp = tid >> 5;
    const int lane = tid & 31;
    const int m0 = blockIdx.y * 128;
    const int n0 = blockIdx.x * 128;
    const int wm0 = (warp >> 2) * 64;
    const int wn0 = (warp & 3) * 32;

    // staging: thread t -> smem row t (A rows 0-127, B rows 128-255)
    const __half* gsrc = (tid < 128)
        ? jb.A  + (size_t)(m0 + tid) * K
        : jb.Bt + (size_t)(n0 + tid - 128) * K;
    const unsigned smb = sptr(sm);
    const unsigned sdst = smb + (unsigned)tid * APB;

    // fragment lane mapping (fp16 m16n8k16)
    const int arow = lane & 15;
    const int ac16 = ((lane >> 4) & 1) * 16;           // bytes: col8 halves
    const int brow = (lane & 7) + ((lane >> 4) & 1) * 8;
    const int bk16 = ((lane >> 3) & 1) * 16;           // bytes

    float acc[4][4][4];
    #pragma unroll
    for (int mt = 0; mt < 4; mt++)
        #pragma unroll
        for (int nt = 0; nt < 4; nt++)
            #pragma unroll
            for (int i = 0; i < 4; i++) acc[mt][nt][i] = 0.0f;

    const int T = K / 64;
    auto issue = [&](int st) {
        if (st < T) {
            const unsigned off = (unsigned)((st % 3) * STGH) * 2;
            const int ko = st * 64;
            #pragma unroll
            for (int i = 0; i < 8; i++)
                CP_ASYNC16(sdst + off + i * 16, gsrc + ko + i * 8);
        }
        CP_COMMIT();
    };

    issue(0);
    issue(1);

    for (int t = 0; t < T; t++) {
        CP_WAIT1();
        __syncthreads();
        issue(t + 2);

        const unsigned so = (unsigned)((t % 3) * STGH) * 2;
        const unsigned ab = smb + so + (unsigned)(wm0 + arow) * APB + ac16;
        const unsigned bb = smb + so + (unsigned)(128 + wn0 + brow) * APB + bk16;
        #pragma unroll
        for (int ks = 0; ks < 4; ks++) {
            unsigned a[4][4];
            #pragma unroll
            for (int mt = 0; mt < 4; mt++)
                ldsm4(a[mt][0], a[mt][1], a[mt][2], a[mt][3],
                      ab + (unsigned)(mt * 16 * APB + ks * 32));
            #pragma unroll
            for (int ntp = 0; ntp < 2; ntp++) {
                unsigned b0, b1, b2, b3;
                ldsm4(b0, b1, b2, b3, bb + (unsigned)(ntp * 16 * APB + ks * 32));
                unsigned ba[2] = {b0, b1}, bx[2] = {b2, b3};
                #pragma unroll
                for (int mt = 0; mt < 4; mt++) {
                    mmah(acc[mt][2 * ntp],     a[mt], ba);
                    mmah(acc[mt][2 * ntp + 1], a[mt], bx);
                }
            }
        }
        __syncthreads();
    }

    #pragma unroll
    for (int mt = 0; mt < 4; mt++) {
        #pragma unroll
        for (int nt = 0; nt < 4; nt++) {
            int r0 = m0 + wm0 + mt * 16 + (lane >> 2);
            int c0 = n0 + wn0 + nt * 8 + 2 * (lane & 3);
            float b0 = jb.bias[c0], b1 = jb.bias[c0 + 1];
            float v0 = acc[mt][nt][0] + b0, v1 = acc[mt][nt][1] + b1;
            float v2 = acc[mt][nt][2] + b0, v3 = acc[mt][nt][3] + b1;
            size_t p0 = (size_t)r0 * N + c0;
            size_t p1 = (size_t)(r0 + 8) * N + c0;
            if (jb.CH) {
                *(unsigned*)&jb.CH[p0] = f22h2(v0, v1);
                *(unsigned*)&jb.CH[p1] = f22h2(v2, v3);
            }
            if (jb.CT) {
                jb.CT[(size_t)c0 * M + r0]           = __float2half_rn(v0);
                jb.CT[(size_t)(c0 + 1) * M + r0]     = __float2half_rn(v1);
                jb.CT[(size_t)c0 * M + r0 + 8]       = __float2half_rn(v2);
                jb.CT[(size_t)(c0 + 1) * M + r0 + 8] = __float2half_rn(v3);
            }
            if (jb.C) {
                float2 w0 = {v0, v1}, w1 = {v2, v3};
                *(float2*)&jb.C[p0] = w0;
                *(float2*)&jb.C[p1] = w1;
            }
        }
    }
}

// ---------------------------------------------------------------------------
// Final gate GEMM (fp16): gpre = gph + rec_h @ WgT_hi^T (K=1024), then
// dst = out + sigmoid(gpre) * (rec - out).
// ---------------------------------------------------------------------------
__global__ void __launch_bounds__(256, 2) gate_fin_kernel(
    const __half* __restrict__ recH, const __half* __restrict__ WgT_hi,
    const float* __restrict__ gph,
    const float* __restrict__ outF, const float* __restrict__ recF,
    float* __restrict__ dst, int N)
{
    extern __shared__ unsigned sm[];

    const int tid  = threadIdx.x;
    const int warp = tid >> 5;
    const int lane = tid & 31;
    const int m0 = blockIdx.y * 128;
    const int n0 = blockIdx.x * 128;
    const int wm0 = (warp >> 2) * 64;
    const int wn0 = (warp & 3) * 32;

    const __half* gsrc = (tid < 128)
        ? recH   + (size_t)(m0 + tid) * HID
        : WgT_hi + (size_t)(n0 + tid - 128) * HID;
    const unsigned smb = sptr(sm);
    const unsigned sdst = smb + (unsigned)tid * APB;

    const int arow = lane & 15;
    const int ac16 = ((lane >> 4) & 1) * 16;
    const int brow = (lane & 7) + ((lane >> 4) & 1) * 8;
    const int bk16 = ((lane >> 3) & 1) * 16;

    float acc[4][4][4];
    #pragma unroll
    for (int mt = 0; mt < 4; mt++)
        #pragma unroll
        for (int nt = 0; nt < 4; nt++)
            #pragma unroll
            for (int i = 0; i < 4; i++) acc[mt][nt][i] = 0.0f;

    const int T = HID / 64;
    auto issue = [&](int st) {
        if (st < T) {
            const unsigned off = (unsigned)((st % 3) * STGH) * 2;
            const int ko = st * 64;
            #pragma unroll
            for (int i = 0; i < 8; i++)
                CP_ASYNC16(sdst + off + i * 16, gsrc + ko + i * 8);
        }
        CP_COMMIT();
    };

    issue(0);
    issue(1);

    for (int t = 0; t < T; t++) {
        CP_WAIT1();
        __syncthreads();
        issue(t + 2);

        const unsigned so = (unsigned)((t % 3) * STGH) * 2;
        const unsigned ab = smb + so + (unsigned)(wm0 + arow) * APB + ac16;
        const unsigned bb = smb + so + (unsigned)(128 + wn0 + brow) * APB + bk16;
        #pragma unroll
        for (int ks = 0; ks < 4; ks++) {
            unsigned a[4][4];
            #pragma unroll
            for (int mt = 0; mt < 4; mt++)
                ldsm4(a[mt][0], a[mt][1], a[mt][2], a[mt][3],
                      ab + (unsigned)(mt * 16 * APB + ks * 32));
            #pragma unroll
            for (int ntp = 0; ntp < 2; ntp++) {
                unsigned b0, b1, b2, b3;
                ldsm4(b0, b1, b2, b3, bb + (unsigned)(ntp * 16 * APB + ks * 32));
                unsigned ba[2] = {b0, b1}, bx[2] = {b2, b3};
                #pragma unroll
                for (int mt = 0; mt < 4; mt++) {
                    mmah(acc[mt][2 * ntp],     a[mt], ba);
                    mmah(acc[mt][2 * ntp + 1], a[mt], bx);
                }
            }
        }
        __syncthreads();
    }

    #pragma unroll
    for (int mt = 0; mt < 4; mt++) {
        #pragma unroll
        for (int nt = 0; nt < 4; nt++) {
            int r0 = m0 + wm0 + mt * 16 + (lane >> 2);
            int c0 = n0 + wn0 + nt * 8 + 2 * (lane & 3);
            size_t p0 = (size_t)r0 * N + c0;
            size_t p1 = (size_t)(r0 + 8) * N + c0;
            float2 h0 = *(const float2*)&gph[p0];
            float2 h1 = *(const float2*)&gph[p1];
            float gp0 = acc[mt][nt][0] + h0.x, gp1 = acc[mt][nt][1] + h0.y;
            float gp2 = acc[mt][nt][2] + h1.x, gp3 = acc[mt][nt][3] + h1.y;
            float2 o0 = *(const float2*)&outF[p0];
            float2 o1 = *(const float2*)&outF[p1];
            float2 rc0 = *(const float2*)&recF[p0];
            float2 rc1 = *(const float2*)&recF[p1];
            float gg0 = 1.0f / (1.0f + ex2f(-gp0 * LOG2E));
            float gg1 = 1.0f / (1.0f + ex2f(-gp1 * LOG2E));
            float gg2 = 1.0f / (1.0f + ex2f(-gp2 * LOG2E));
            float gg3 = 1.0f / (1.0f + ex2f(-gp3 * LOG2E));
            float2 w0 = {o0.x + gg0 * (rc0.x - o0.x), o0.y + gg1 * (rc0.y - o0.y)};
            float2 w1 = {o1.x + gg2 * (rc1.x - o1.x), o1.y + gg3 * (rc1.y - o1.y)};
            *(float2*)&dst[p0] = w0;
            *(float2*)&dst[p1] = w1;
        }
    }
}

// ---------------------------------------------------------------------------
// fp16 flash attention: 256 thr, 128 queries/block, 64-key tiles, Vt
// pre-transposed ([h][d][keys]). K/Vt cp.async double-buffered. m16n8k16.
// ---------------------------------------------------------------------------
#define QPH 72
#define QPB (QPH * 2)
#define ATTN_SMEM ((128 + 128 + 128) * QPB)   // Q/P + 2xK + 2xVt = 55,296 B

__global__ void __launch_bounds__(256, 2) attn_h_kernel(
    const __half* __restrict__ Q, const __half* __restrict__ K,
    const __half* __restrict__ Vt, __half* __restrict__ O, int Mv)
{
    extern __shared__ unsigned sm[];
    const unsigned smb = sptr(sm);
    const unsigned KB0 = 128 * QPB;            // K buffers byte offset
    const unsigned VB0 = 256 * QPB;            // Vt buffers byte offset
    __half* QPh = (__half*)sm;

    const size_t zoff = (size_t)blockIdx.z * SH;
    K += zoff; O += zoff;

    const int tid  = threadIdx.x;
    const int warp = tid >> 5;
    const int lane = tid & 31;
    const int hoff = blockIdx.y * HDIM;
    const int q0   = blockIdx.x * 128;

    const __half* Vtb = Vt + (size_t)hoff * Mv + (size_t)blockIdx.z * S_LEN;

    const int arow = lane & 15;
    const int ac16 = ((lane >> 4) & 1) * 16;
    const int brow = (lane & 7) + ((lane >> 4) & 1) * 8;
    const int bk16 = ((lane >> 3) & 1) * 16;

    const int krow = tid >> 2;          // 0..63
    const int kq   = (tid & 3) * 16;    // halves (32B)

    // Stage Q (128 rows x 64 halves)
    {
        const int row = tid >> 1, half = tid & 1;
        const uint4* Qg = (const uint4*)(Q + (size_t)(q0 + row) * HID + hoff) + half * 4;
        uint4* Qs = (uint4*)&QPh[row * QPH + half * 32];
        #pragma unroll
        for (int j = 0; j < 4; j++) Qs[j] = Qg[j];
    }

    auto issueKV = [&](int s) {
        const unsigned bo = (unsigned)((s & 1) * 64 * QPB);
        unsigned kd = smb + KB0 + bo + (unsigned)krow * QPB + kq * 2;
        const __half* kg = K + (size_t)(s * 64 + krow) * HID + hoff + kq;
        CP_ASYNC16(kd,      kg);
        CP_ASYNC16(kd + 16, kg + 8);
        unsigned vd = smb + VB0 + bo + (unsigned)krow * QPB + kq * 2;
        const __half* vg = Vtb + (size_t)krow * Mv + s * 64 + kq;
        CP_ASYNC16(vd,      vg);
        CP_ASYNC16(vd + 16, vg + 8);
    };

    issueKV(0);
    CP_COMMIT();
    __syncthreads();

    // Resident Q fragments (4 k-steps)
    unsigned qa[4][4];
    {
        unsigned base = smb + (unsigned)(warp * 16 + arow) * QPB + ac16;
        #pragma unroll
        for (int g = 0; g < 4; g++)
            ldsm4(qa[g][0], qa[g][1], qa[g][2], qa[g][3], base + g * 32);
    }

    float o[8][4];
    #pragma unroll
    for (int nt = 0; nt < 8; nt++)
        #pragma unroll
        for (int i = 0; i < 4; i++) o[nt][i] = 0.0f;
    float mrow0 = -1e30f, mrow1 = -1e30f, lrow0 = 0.0f, lrow1 = 0.0f;

    const unsigned pbase  = smb + (unsigned)(warp * 16 + arow) * QPB + ac16;
    const unsigned kbase0 = smb + KB0 + (unsigned)brow * QPB + bk16;
    const unsigned vbase0 = smb + VB0 + (unsigned)brow * QPB + bk16;

    const int T = S_LEN / 64;
    for (int tile = 0; tile < T; tile++) {
        CP_WAIT0();
        __syncthreads();
        if (tile + 1 < T) issueKV(tile + 1);
        CP_COMMIT();

        const unsigned so = (unsigned)((tile & 1) * 64 * QPB);

        // --- S = Q K^T ---
        float s[8][4];
        #pragma unroll
        for (int nt = 0; nt < 8; nt++)
            #pragma unroll
            for (int i = 0; i < 4; i++) s[nt][i] = 0.0f;

        {
            const unsigned kbase = kbase0 + so;
            #pragma unroll
            for (int g = 0; g < 4; g++) {
                #pragma unroll
                for (int ntp = 0; ntp < 4; ntp++) {
                    unsigned b0, b1, b2, b3;
                    ldsm4(b0, b1, b2, b3, kbase + (unsigned)(ntp * 16 * QPB + g * 32));
                    unsigned ba[2] = {b0, b1}, bb[2] = {b2, b3};
                    mmah(s[2 * ntp],     qa[g], ba);
                    mmah(s[2 * ntp + 1], qa[g], bb);
                }
            }
        }

        // --- Online softmax (log2 domain) ---
        float mx0 = -1e30f, mx1 = -1e30f;
        #pragma unroll
        for (int nt = 0; nt < 8; nt++) {
            s[nt][0] *= SCL2; s[nt][1] *= SCL2;
            s[nt][2] *= SCL2; s[nt][3] *= SCL2;
            mx0 = fmaxf(mx0, fmaxf(s[nt][0], s[nt][1]));
            mx1 = fmaxf(mx1, fmaxf(s[nt][2], s[nt][3]));
        }
        mx0 = fmaxf(mx0, __shfl_xor_sync(0xffffffffu, mx0, 1));
        mx0 = fmaxf(mx0, __shfl_xor_sync(0xffffffffu, mx0, 2));
        mx1 = fmaxf(mx1, __shfl_xor_sync(0xffffffffu, mx1, 1));
        mx1 = fmaxf(mx1, __shfl_xor_sync(0xffffffffu, mx1, 2));

        float mn0 = fmaxf(mrow0, mx0);
        float mn1 = fmaxf(mrow1, mx1);
        float a0 = ex2f(mrow0 - mn0);
        float a1 = ex2f(mrow1 - mn1);

        {
            const int pr = lane >> 2;
            const int pc = 2 * (lane & 3);
            __half* P0 = &QPh[(warp * 16 + pr) * QPH + pc];
            __half* P1 = &QPh[(warp * 16 + pr + 8) * QPH + pc];
            float rs0 = 0.0f, rs1 = 0.0f;
            #pragma unroll
            for (int nt = 0; nt < 8; nt++) {
                float p0 = ex2f(s[nt][0] - mn0);
                float p1 = ex2f(s[nt][1] - mn0);
                float p2 = ex2f(s[nt][2] - mn1);
                float p3 = ex2f(s[nt][3] - mn1);
                rs0 += p0 + p1;
                rs1 += p2 + p3;
                *(unsigned*)(P0 + nt * 8) = f22h2(p0, p1);
                *(unsigned*)(P1 + nt * 8) = f22h2(p2, p3);
            }
            rs0 += __shfl_xor_sync(0xffffffffu, rs0, 1);
            rs0 += __shfl_xor_sync(0xffffffffu, rs0, 2);
            rs1 += __shfl_xor_sync(0xffffffffu, rs1, 1);
            rs1 += __shfl_xor_sync(0xffffffffu, rs1, 2);
            lrow0 = lrow0 * a0 + rs0;
            lrow1 = lrow1 * a1 + rs1;
            mrow0 = mn0; mrow1 = mn1;
        }
        #pragma unroll
        for (int nt = 0; nt < 8; nt++) {
            o[nt][0] *= a0; o[nt][1] *= a0;
            o[nt][2] *= a1; o[nt][3] *= a1;
        }
        __syncwarp();

        // --- O += P @ V ---
        {
            const unsigned vbase = vbase0 + so;
            #pragma unroll
            for (int g = 0; g < 4; g++) {
                unsigned pa[4];
                ldsm4(pa[0], pa[1], pa[2], pa[3], pbase + g * 32);
                #pragma unroll
                for (int ntp = 0; ntp < 4; ntp++) {
                    unsigned b0, b1, b2, b3;
                    ldsm4(b0, b1, b2, b3, vbase + (unsigned)(ntp * 16 * QPB + g * 32));
                    unsigned ba[2] = {b0, b1}, bb[2] = {b2, b3};
                    mmah(o[2 * ntp],     pa, ba);
                    mmah(o[2 * ntp + 1], pa, bb);
                }
            }
        }
    }

    // Write O (fp16)
    float i0 = 1.0f / lrow0;
    float i1 = 1.0f / lrow1;
    int r0 = q0 + warp * 16 + (lane >> 2);
    #pragma unroll
    for (int nt = 0; nt < 8; nt++) {
        int c = hoff + nt * 8 + 2 * (lane & 3);
        *(unsigned*)&O[(size_t)r0 * HID + c]       = f22h2(o[nt][0] * i0, o[nt][1] * i0);
        *(unsigned*)&O[(size_t)(r0 + 8) * HID + c] = f22h2(o[nt][2] * i1, o[nt][3] * i1);
    }
}

// ---------------------------------------------------------------------------
// Combine: rec = 0.5*(a+b) from fp16 inputs -> fp32 + fp16 copies
// ---------------------------------------------------------------------------
__global__ void combine_kernel(const uint2* __restrict__ a,
                               const uint2* __restrict__ b,
                               float4* __restrict__ oF,
                               uint2* __restrict__ oH, int n4)
{
    int i = blockIdx.x * blockDim.x + threadIdx.x;
    if (i < n4) {
        uint2 ua = a[i], ub = b[i];
        __half2 a0 = *(__half2*)&ua.x, a1 = *(__half2*)&ua.y;
        __half2 b0 = *(__half2*)&ub.x, b1 = *(__half2*)&ub.y;
        float2 f0 = __half22float2(a0), f1 = __half22float2(a1);
        float2 g0 = __half22float2(b0), g1 = __half22float2(b1);
        float4 r;
        r.x = 0.5f * (f0.x + g0.x); r.y = 0.5f * (f0.y + g0.y);
        r.z = 0.5f * (f1.x + g1.x); r.w = 0.5f * (f1.y + g1.y);
        oF[i] = r;
        uint2 w = {f22h2(r.x, r.y), f22h2(r.z, r.w)};
        oH[i] = w;
    }
}

// ---------------------------------------------------------------------------
// Launch — dual-stream fork/join (same DAG as round 11), fp16 operands.
// ---------------------------------------------------------------------------
extern "C" void kernel_launch(void* const* d_in, const int* in_sizes, int n_in,
                              void* d_out, int out_size)
{
    (void)in_sizes; (void)n_in; (void)out_size;

    const float* hs   = (const float*)d_in[0];
    const float* past = (const float*)d_in[1];
    const float* Wq = (const float*)d_in[2];  const float* bq = (const float*)d_in[3];
    const float* Wk = (const float*)d_in[4];  const float* bk = (const float*)d_in[5];
    const float* Wv = (const float*)d_in[6];  const float* bv = (const float*)d_in[7];
    const float* Wo = (const float*)d_in[8];  const float* bo = (const float*)d_in[9];
    const float* Wrq = (const float*)d_in[10]; const float* brq = (const float*)d_in[11];
    const float* Wrk = (const float*)d_in[12]; const float* brk = (const float*)d_in[13];
    const float* Wrv = (const float*)d_in[14]; const float* brv = (const float*)d_in[15];
    const float* Wg = (const float*)d_in[16];  const float* bg = (const float*)d_in[17];

    __half *wt, *wo_h, *wor_t, *hs_h, *past_h, *q, *k, *vt, *ctx_h, *out_h,
           *rq, *rk, *rvt, *rctx, *rec_h;
    float *bor, *zero, *out, *gpre, *rec;
    cudaGetSymbolAddress((void**)&wt,     g_wt);
    cudaGetSymbolAddress((void**)&wo_h,   g_wo_h);
    cudaGetSymbolAddress((void**)&wor_t,  g_wor_t);
    cudaGetSymbolAddress((void**)&bor,    g_bor);
    cudaGetSymbolAddress((void**)&zero,   g_zero);
    cudaGetSymbolAddress((void**)&hs_h,   g_hs_h);
    cudaGetSymbolAddress((void**)&past_h, g_past_h);
    cudaGetSymbolAddress((void**)&q,      g_q);
    cudaGetSymbolAddress((void**)&k,      g_k);
    cudaGetSymbolAddress((void**)&vt,     g_vt);
    cudaGetSymbolAddress((void**)&ctx_h,  g_ctx_h);
    cudaGetSymbolAddress((void**)&out,    g_out);
    cudaGetSymbolAddress((void**)&out_h,  g_out_h);
    cudaGetSymbolAddress((void**)&gpre,   g_gpre);
    cudaGetSymbolAddress((void**)&rq,     g_rq);
    cudaGetSymbolAddress((void**)&rk,     g_rk);
    cudaGetSymbolAddress((void**)&rvt,    g_rvt);
    cudaGetSymbolAddress((void**)&rctx,   g_rctx);
    cudaGetSymbolAddress((void**)&rec,    g_rec);
    cudaGetSymbolAddress((void**)&rec_h,  g_rec_h);

    cudaFuncSetAttribute(attn_h_kernel,
                         cudaFuncAttributeMaxDynamicSharedMemorySize, ATTN_SMEM);
    cudaFuncSetAttribute(gemm_h_kernel,
                         cudaFuncAttributeMaxDynamicSharedMemorySize, GSMEMH);
    cudaFuncSetAttribute(gate_fin_kernel,
                         cudaFuncAttributeMaxDynamicSharedMemorySize, GSMEMH);

    cudaStream_t sB;
    cudaStreamCreateWithFlags(&sB, cudaStreamNonBlocking);
    cudaEvent_t evFork, evWor, evJoin, evOut, evGp;
    cudaEventCreateWithFlags(&evFork, cudaEventDisableTiming);
    cudaEventCreateWithFlags(&evWor,  cudaEventDisableTiming);
    cudaEventCreateWithFlags(&evJoin, cudaEventDisableTiming);
    cudaEventCreateWithFlags(&evOut,  cudaEventDisableTiming);
    cudaEventCreateWithFlags(&evGp,   cudaEventDisableTiming);

    #define WT(i) (wt + (size_t)(i) * HID * HID)

    // --- prep (main stream): weight transpose+convert ---
    {
        P9 ws = {{Wq, Wk, Wv, Wo, Wrq, Wrk, Wrv, Wg, Wg + (size_t)HID * HID}};
        prep_wt_kernel<<<dim3(32, 32, 9), 256>>>(ws, wt);
    }
    cudaEventRecord(evFork, cudaStreamPerThread);
    cudaStreamWaitEvent(sB, evFork, 0);

    prep_h_kernel<<<SH / 4 / 256, 256>>>((const float4*)hs, (uint2*)hs_h, SH / 4);

    // --- stream B: past prep, Wo fp16, W_or fusion, b_or, rk/rvt GEMM ---
    prep_h_kernel<<<2 * SH / 4 / 256, 256, 0, sB>>>(
        (const float4*)past, (uint2*)past_h, 2 * SH / 4);
    prep_h_kernel<<<HID * HID / 4 / 256, 256, 0, sB>>>(
        (const float4*)Wo, (uint2*)wo_h, HID * HID / 4);
    {
        GJ3 gj = {{{WT(4), wo_h, zero, 0, wor_t, 0}, {}, {}}};
        gemm_h_kernel<<<dim3(8, 8, 1), 256, GSMEMH, sB>>>(gj, HID, HID, HID);
    }
    bor_kernel<<<HID / 256, 256, 0, sB>>>(bo, Wrq, brq, bor);
    cudaEventRecord(evWor, sB);
    {
        GJ3 gj = {{{past_h, WT(5), brk, 0, rk, 0},
                   {past_h, WT(6), brv, 0, 0, rvt}, {}}};
        gemm_h_kernel<<<dim3(8, 32, 2), 256, GSMEMH, sB>>>(gj, 2 * S_LEN, HID, HID);
    }
    cudaEventRecord(evJoin, sB);

    // --- main stream: self attention chain ---
    {
        GJ3 gj = {{{hs_h, WT(0), bq, 0, q, 0},
                   {hs_h, WT(1), bk, 0, k, 0},
                   {hs_h, WT(2), bv, 0, 0, vt}}};
        gemm_h_kernel<<<dim3(8, 16, 3), 256, GSMEMH>>>(gj, S_LEN, HID, HID);
    }
    attn_h_kernel<<<dim3(16, 16, 1), 256, ATTN_SMEM>>>(q, k, vt, ctx_h, S_LEN);

    cudaStreamWaitEvent(cudaStreamPerThread, evWor, 0);
    {
        GJ3 gj = {{{ctx_h, WT(3), bo, out, out_h, 0},
                   {ctx_h, wor_t, bor, 0, rq, 0}, {}}};
        gemm_h_kernel<<<dim3(8, 16, 2), 256, GSMEMH>>>(gj, S_LEN, HID, HID);
    }
    cudaEventRecord(evOut, cudaStreamPerThread);

    // --- stream B: gpre_half = out_h @ Wg_lo + bg (overlaps attn2) ---
    cudaStreamWaitEvent(sB, evOut, 0);
    {
        GJ3 gj = {{{out_h, WT(7), bg, gpre, 0, 0}, {}, {}}};
        gemm_h_kernel<<<dim3(8, 16, 1), 256, GSMEMH, sB>>>(gj, S_LEN, HID, HID);
    }
    cudaEventRecord(evGp, sB);

    // --- main stream: recursive attention ---
    cudaStreamWaitEvent(cudaStreamPerThread, evJoin, 0);
    attn_h_kernel<<<dim3(16, 16, 2), 256, ATTN_SMEM>>>(rq, rk, rvt, rctx,
                                                       2 * S_LEN);
    combine_kernel<<<SH / 4 / 256, 256>>>((const uint2*)rctx,
                                          (const uint2*)(rctx + SH),
                                          (float4*)rec, (uint2*)rec_h, SH / 4);

    // --- final gate (rec half) + blend -> d_out ---
    cudaStreamWaitEvent(cudaStreamPerThread, evGp, 0);
    gate_fin_kernel<<<dim3(8, 16), 256, GSMEMH>>>(rec_h, WT(8), gpre,
                                                  out, rec, (float*)d_out, HID);
}